// round 1
// baseline (speedup 1.0000x reference)
#include <cuda_runtime.h>
#include <cuda_bf16.h>

#define S 3072
#define DIM 1536
#define H 12
#define HD 128
#define NB 24
#define BLK 128
#define SCALE 0.08838834764831845f   // 1/sqrt(128)
#define NEG_BIG (-1e30f)

// ---------------- scratch (device globals; no allocation allowed) ----------
__device__ float g_q[S * DIM];
__device__ float g_k[S * DIM];
__device__ float g_v[S * DIM];
__device__ float g_att[S * DIM];
__device__ float g_qw[NB * DIM];
__device__ float g_kw[NB * DIM];
__device__ float g_battn[H * NB * NB];
__device__ float g_thr[H];
__device__ int   g_list[H * NB * NB];
__device__ int   g_cnt[H * NB];

// ---------------------------------------------------------------------------
// GEMM: C[m][n] = sum_k A[m][k] * W[n][k] + bias[n]   (M=3072, N=K=1536)
// 128x128 tile, KT=16, 256 threads, 8x8 per thread via packed fma.rn.f32x2.
// ---------------------------------------------------------------------------
__global__ __launch_bounds__(256, 2) void gemm_nt(
    const float* __restrict__ A, const float* __restrict__ W,
    const float* __restrict__ bias, float* __restrict__ C)
{
    __shared__ float As[128][17];   // [m][k], odd stride -> conflict-free col reads
    __shared__ float Bs[16][132];   // [k][n] transposed; 132 even -> 8B-aligned pairs

    const int n0 = blockIdx.x * 128;
    const int m0 = blockIdx.y * 128;
    const int tid = threadIdx.x;
    const int tx = tid & 15;
    const int ty = tid >> 4;

    unsigned long long acc[8][4];
#pragma unroll
    for (int i = 0; i < 8; i++)
#pragma unroll
        for (int j = 0; j < 4; j++) acc[i][j] = 0ULL;

    for (int k0 = 0; k0 < 1536; k0 += 16) {
#pragma unroll
        for (int u = 0; u < 2; u++) {
            int f = tid + 256 * u;
            int row = f >> 2;
            int q = (f & 3) << 2;
            float4 va = *(const float4*)(A + (size_t)(m0 + row) * 1536 + k0 + q);
            As[row][q + 0] = va.x; As[row][q + 1] = va.y;
            As[row][q + 2] = va.z; As[row][q + 3] = va.w;
            float4 vb = *(const float4*)(W + (size_t)(n0 + row) * 1536 + k0 + q);
            Bs[q + 0][row] = vb.x; Bs[q + 1][row] = vb.y;
            Bs[q + 2][row] = vb.z; Bs[q + 3][row] = vb.w;
        }
        __syncthreads();
#pragma unroll
        for (int kk = 0; kk < 16; kk++) {
            unsigned long long ap[8], bp[4];
#pragma unroll
            for (int i = 0; i < 8; i++) {
                float a = As[ty + 16 * i][kk];
                asm("mov.b64 %0, {%1, %1};" : "=l"(ap[i]) : "f"(a));
            }
#pragma unroll
            for (int j = 0; j < 4; j++)
                bp[j] = *(const unsigned long long*)&Bs[kk][2 * tx + 32 * j];
#pragma unroll
            for (int i = 0; i < 8; i++)
#pragma unroll
                for (int j = 0; j < 4; j++)
                    asm("fma.rn.f32x2 %0, %1, %2, %0;"
                        : "+l"(acc[i][j]) : "l"(ap[i]), "l"(bp[j]));
        }
        __syncthreads();
    }

#pragma unroll
    for (int i = 0; i < 8; i++) {
        int row = m0 + ty + 16 * i;
#pragma unroll
        for (int j = 0; j < 4; j++) {
            int col = n0 + 2 * tx + 32 * j;
            float lo, hi;
            asm("mov.b64 {%0, %1}, %2;" : "=f"(lo), "=f"(hi) : "l"(acc[i][j]));
            float2 o;
            o.x = lo + bias[col];
            o.y = hi + bias[col + 1];
            *(float2*)(C + (size_t)row * 1536 + col) = o;
        }
    }
}

// ---------------------------------------------------------------------------
// RMSNorm (full 1536 dim) + RoPE (per-head, interleaved pairs), in place.
// grid (S, 2): y=0 -> q, y=1 -> k.  256 threads.
// ---------------------------------------------------------------------------
__global__ __launch_bounds__(256) void norm_rope_kernel(
    float* __restrict__ Xq, float* __restrict__ Xk,
    const float* __restrict__ gq, const float* __restrict__ gk,
    const float* __restrict__ fc, const float* __restrict__ fs)
{
    const int s = blockIdx.x;
    float* X = blockIdx.y ? Xk : Xq;
    const float* g = blockIdx.y ? gk : gq;
    float* row = X + (size_t)s * 1536;
    const int tid = threadIdx.x;

    float ss = 0.f;
#pragma unroll
    for (int c = 0; c < 6; c++) {
        float v = row[tid + 256 * c];
        ss += v * v;
    }
#pragma unroll
    for (int o = 16; o >= 1; o >>= 1)
        ss += __shfl_xor_sync(0xffffffffu, ss, o);
    __shared__ float red[8];
    if ((tid & 31) == 0) red[tid >> 5] = ss;
    __syncthreads();
    float tot = 0.f;
#pragma unroll
    for (int w = 0; w < 8; w++) tot += red[w];
    float scale = rsqrtf(tot * (1.f / 1536.f) + 1e-5f);

#pragma unroll
    for (int u = 0; u < 3; u++) {
        int p = tid + 256 * u;          // pair index 0..767, elements 2p, 2p+1
        int i = p & 63;                 // rotation index within head
        float c = fc[s * 64 + i];
        float sn = fs[s * 64 + i];
        float x0 = row[2 * p] * scale * g[2 * p];
        float x1 = row[2 * p + 1] * scale * g[2 * p + 1];
        row[2 * p]     = x0 * c - x1 * sn;
        row[2 * p + 1] = x0 * sn + x1 * c;
    }
}

// ---------------------------------------------------------------------------
// Block mean pooling: qw[nb][d] = mean over 128 tokens. grid (NB, 2), 256 thr.
// ---------------------------------------------------------------------------
__global__ __launch_bounds__(256) void pool_mean(
    const float* __restrict__ Q, const float* __restrict__ Kx,
    float* __restrict__ qw, float* __restrict__ kw)
{
    const int nb = blockIdx.x;
    const float* X = blockIdx.y ? Kx : Q;
    float* Wo = blockIdx.y ? kw : qw;
    const int tid = threadIdx.x;
    float acc[6] = {0, 0, 0, 0, 0, 0};
    for (int t = 0; t < 128; t++) {
        const float* row = X + (size_t)(nb * 128 + t) * 1536;
#pragma unroll
        for (int c = 0; c < 6; c++) acc[c] += row[tid + 256 * c];
    }
#pragma unroll
    for (int c = 0; c < 6; c++)
        Wo[nb * 1536 + tid + 256 * c] = acc[c] * (1.f / 128.f);
}

// ---------------------------------------------------------------------------
// Draft scores + local mask + row softmax. grid (H, NB), 32 threads (lane=m).
// ---------------------------------------------------------------------------
__global__ void draft_scores(const float* __restrict__ qw,
                             const float* __restrict__ kw,
                             float* __restrict__ battn)
{
    const int h = blockIdx.x, l = blockIdx.y;
    const int m = threadIdx.x;
    float sc = NEG_BIG;
    if (m < 24) {
        int rl = l >> 2, cl = l & 3, rm = m >> 2, cm = m & 3;
        bool ok = (rm >= rl - 3) && (rm <= rl + 2) && (cm >= cl - 3) && (cm <= cl + 2);
        if (ok) {
            float sum = 0.f;
            const float* qr = qw + l * 1536 + h * 128;
            const float* kr = kw + m * 1536 + h * 128;
#pragma unroll 8
            for (int d = 0; d < 128; d++) sum += qr[d] * kr[d];
            sc = sum * SCALE;
        }
    }
    float mx = sc;
#pragma unroll
    for (int o = 16; o >= 1; o >>= 1)
        mx = fmaxf(mx, __shfl_xor_sync(0xffffffffu, mx, o));
    float e = __expf(sc - mx);              // masked -> exp(-huge)=0
    float se = e;
#pragma unroll
    for (int o = 16; o >= 1; o >>= 1)
        se += __shfl_xor_sync(0xffffffffu, se, o);
    if (m < 24) battn[(h * 24 + l) * 24 + m] = e / se;
}

// ---------------------------------------------------------------------------
// Per-head top-k threshold: thr = 129th largest of 576 values (counting ties
// exactly as sorted-order top_k does). grid H, 256 threads.
// ---------------------------------------------------------------------------
__global__ void topk_thresh(const float* __restrict__ battn, float* __restrict__ thr)
{
    const int h = blockIdx.x;
    __shared__ float buf[576];
    __shared__ float result;
    for (int e = threadIdx.x; e < 576; e += 256) buf[e] = battn[h * 576 + e];
    if (threadIdx.x == 0) result = 0.f;
    __syncthreads();
    for (int e = threadIdx.x; e < 576; e += 256) {
        float v = buf[e];
        int cg = 0, ce = 0;
        for (int x = 0; x < 576; x++) {
            cg += (buf[x] > v);
            ce += (buf[x] == v);
        }
        if (cg <= 128 && cg + ce >= 129) result = v;   // all writers write same value
    }
    __syncthreads();
    if (threadIdx.x == 0) thr[h] = result;
}

// ---------------------------------------------------------------------------
// Compact selected key-block lists per (h, l). grid (NB, H), 32 threads.
// ---------------------------------------------------------------------------
__global__ void build_lists(const float* __restrict__ battn,
                            const float* __restrict__ thr,
                            int* __restrict__ list, int* __restrict__ cnt)
{
    const int l = blockIdx.x, h = blockIdx.y;
    const int m = threadIdx.x;
    bool sel = (m < 24) && (battn[(h * 24 + l) * 24 + m] > thr[h]);
    unsigned msk = __ballot_sync(0xffffffffu, sel);
    int pos = __popc(msk & ((1u << m) - 1u));
    if (sel) list[(h * 24 + l) * 24 + pos] = m;
    if (m == 0) cnt[h * 24 + l] = __popc(msk);
}

// ---------------------------------------------------------------------------
// Block-sparse flash attention. grid (NB, H), 256 threads, 194KB dyn smem.
// Each CTA: one (query-block, head); streams selected 128x128 key blocks.
// ---------------------------------------------------------------------------
#define ATT_SMEM (3 * 128 * 129 * 4)

__global__ __launch_bounds__(256, 1) void attn_sparse(
    const float* __restrict__ Qg, const float* __restrict__ Kg,
    const float* __restrict__ Vg, const int* __restrict__ list,
    const int* __restrict__ cnt, float* __restrict__ O)
{
    extern __shared__ float sm[];
    float* Qs = sm;                   // [128][129]
    float* Ks = sm + 128 * 129;       // [128][129], reused as P after S
    float* Vs = sm + 2 * 128 * 129;   // [128][129]

    const int l = blockIdx.x, h = blockIdx.y;
    const int tid = threadIdx.x;
    const int tx = tid & 15;
    const int ty = tid >> 4;

    // load Q block (rows l*128.., head slice h*128..)
#pragma unroll
    for (int u = 0; u < 16; u++) {
        int f = tid + 256 * u;
        int r = f >> 5;
        int d4 = (f & 31) << 2;
        float4 v = *(const float4*)(Qg + (size_t)(l * 128 + r) * 1536 + h * 128 + d4);
        Qs[r * 129 + d4 + 0] = v.x; Qs[r * 129 + d4 + 1] = v.y;
        Qs[r * 129 + d4 + 2] = v.z; Qs[r * 129 + d4 + 3] = v.w;
    }

    float accO[8][8];
    float mrow[8], drow[8];
#pragma unroll
    for (int i = 0; i < 8; i++) {
        mrow[i] = NEG_BIG;
        drow[i] = 0.f;
#pragma unroll
        for (int j = 0; j < 8; j++) accO[i][j] = 0.f;
    }

    const int nc = cnt[h * 24 + l];
    for (int b = 0; b < nc; b++) {
        const int mb = list[(h * 24 + l) * 24 + b];
        __syncthreads();  // prior P/V reads done before overwrite
#pragma unroll
        for (int u = 0; u < 16; u++) {
            int f = tid + 256 * u;
            int r = f >> 5;
            int d4 = (f & 31) << 2;
            float4 vk = *(const float4*)(Kg + (size_t)(mb * 128 + r) * 1536 + h * 128 + d4);
            Ks[r * 129 + d4 + 0] = vk.x; Ks[r * 129 + d4 + 1] = vk.y;
            Ks[r * 129 + d4 + 2] = vk.z; Ks[r * 129 + d4 + 3] = vk.w;
            float4 vv = *(const float4*)(Vg + (size_t)(mb * 128 + r) * 1536 + h * 128 + d4);
            Vs[r * 129 + d4 + 0] = vv.x; Vs[r * 129 + d4 + 1] = vv.y;
            Vs[r * 129 + d4 + 2] = vv.z; Vs[r * 129 + d4 + 3] = vv.w;
        }
        __syncthreads();

        // S = Q K^T
        float s[8][8];
#pragma unroll
        for (int i = 0; i < 8; i++)
#pragma unroll
            for (int j = 0; j < 8; j++) s[i][j] = 0.f;
        for (int d = 0; d < 128; d++) {
            float a[8], bb[8];
#pragma unroll
            for (int i = 0; i < 8; i++) a[i] = Qs[(ty + 16 * i) * 129 + d];
#pragma unroll
            for (int j = 0; j < 8; j++) bb[j] = Ks[(tx + 16 * j) * 129 + d];
#pragma unroll
            for (int i = 0; i < 8; i++)
#pragma unroll
                for (int j = 0; j < 8; j++) s[i][j] += a[i] * bb[j];
        }

        // online softmax update (row state replicated across the 16 lanes of a row)
        float fac[8];
#pragma unroll
        for (int i = 0; i < 8; i++) {
            float rmax = NEG_BIG;
#pragma unroll
            for (int j = 0; j < 8; j++) {
                s[i][j] *= SCALE;
                rmax = fmaxf(rmax, s[i][j]);
            }
#pragma unroll
            for (int o = 8; o >= 1; o >>= 1)
                rmax = fmaxf(rmax, __shfl_xor_sync(0xffffffffu, rmax, o));
            float newm = fmaxf(mrow[i], rmax);
            fac[i] = __expf(mrow[i] - newm);
            float rs = 0.f;
#pragma unroll
            for (int j = 0; j < 8; j++) {
                s[i][j] = __expf(s[i][j] - newm);
                rs += s[i][j];
            }
#pragma unroll
            for (int o = 8; o >= 1; o >>= 1)
                rs += __shfl_xor_sync(0xffffffffu, rs, o);
            drow[i] = drow[i] * fac[i] + rs;
            mrow[i] = newm;
#pragma unroll
            for (int j = 0; j < 8; j++) accO[i][j] *= fac[i];
        }

        __syncthreads();  // done reading Ks
#pragma unroll
        for (int i = 0; i < 8; i++)
#pragma unroll
            for (int j = 0; j < 8; j++)
                Ks[(ty + 16 * i) * 129 + tx + 16 * j] = s[i][j];
        __syncthreads();

        // O += P V
        for (int t = 0; t < 128; t++) {
            float a[8], bb[8];
#pragma unroll
            for (int i = 0; i < 8; i++) a[i] = Ks[(ty + 16 * i) * 129 + t];
#pragma unroll
            for (int j = 0; j < 8; j++) bb[j] = Vs[t * 129 + tx + 16 * j];
#pragma unroll
            for (int i = 0; i < 8; i++)
#pragma unroll
                for (int j = 0; j < 8; j++) accO[i][j] += a[i] * bb[j];
        }
    }

#pragma unroll
    for (int i = 0; i < 8; i++) {
        float inv = drow[i] > 0.f ? 1.f / drow[i] : 0.f;
        int row = l * 128 + ty + 16 * i;
#pragma unroll
        for (int j = 0; j < 8; j++)
            O[(size_t)row * 1536 + h * 128 + tx + 16 * j] = accO[i][j] * inv;
    }
}

// ---------------------------------------------------------------------------
extern "C" void kernel_launch(void* const* d_in, const int* in_sizes, int n_in,
                              void* d_out, int out_size)
{
    const float* x  = (const float*)d_in[0];
    const float* wq = (const float*)d_in[1];
    const float* bq = (const float*)d_in[2];
    const float* wk = (const float*)d_in[3];
    const float* bk = (const float*)d_in[4];
    const float* wv = (const float*)d_in[5];
    const float* bv = (const float*)d_in[6];
    const float* wo = (const float*)d_in[7];
    const float* bo = (const float*)d_in[8];
    const float* gq = (const float*)d_in[9];
    const float* gk = (const float*)d_in[10];
    const float* fc = (const float*)d_in[11];
    const float* fs = (const float*)d_in[12];
    float* out = (float*)d_out;

    float *qp, *kp, *vp, *ap, *qwp, *kwp, *bap, *thp;
    int *lp, *cp;
    cudaGetSymbolAddress((void**)&qp, g_q);
    cudaGetSymbolAddress((void**)&kp, g_k);
    cudaGetSymbolAddress((void**)&vp, g_v);
    cudaGetSymbolAddress((void**)&ap, g_att);
    cudaGetSymbolAddress((void**)&qwp, g_qw);
    cudaGetSymbolAddress((void**)&kwp, g_kw);
    cudaGetSymbolAddress((void**)&bap, g_battn);
    cudaGetSymbolAddress((void**)&thp, g_thr);
    cudaGetSymbolAddress((void**)&lp, g_list);
    cudaGetSymbolAddress((void**)&cp, g_cnt);

    cudaFuncSetAttribute(attn_sparse, cudaFuncAttributeMaxDynamicSharedMemorySize, ATT_SMEM);

    dim3 ggrid(12, 24);   // (N tiles, M tiles)
    gemm_nt<<<ggrid, 256>>>(x, wq, bq, qp);
    gemm_nt<<<ggrid, 256>>>(x, wk, bk, kp);
    gemm_nt<<<ggrid, 256>>>(x, wv, bv, vp);

    norm_rope_kernel<<<dim3(S, 2), 256>>>(qp, kp, gq, gk, fc, fs);
    pool_mean<<<dim3(NB, 2), 256>>>(qp, kp, qwp, kwp);
    draft_scores<<<dim3(H, NB), 32>>>(qwp, kwp, bap);
    topk_thresh<<<H, 256>>>(bap, thp);
    build_lists<<<dim3(NB, H), 32>>>(bap, thp, lp, cp);

    attn_sparse<<<dim3(NB, H), 256, ATT_SMEM>>>(qp, kp, vp, lp, cp, ap);

    gemm_nt<<<ggrid, 256>>>(ap, wo, bo, out);
}

// round 4
// speedup vs baseline: 2.6188x; 2.6188x over previous
#include <cuda_runtime.h>
#include <cuda_bf16.h>
#include <cstdint>

#define S 3072
#define DIM 1536
#define H 12
#define NB 24
#define SCALE 0.08838834764831845f   // 1/sqrt(128)
#define NEG_BIG (-1e30f)

// ---------------- scratch (device globals; no allocation allowed) ----------
__device__ float g_q[S * DIM];
__device__ float g_k[S * DIM];
__device__ float g_v[S * DIM];
__device__ float g_att[S * DIM];
__device__ float g_qw[NB * DIM];
__device__ float g_kw[NB * DIM];
__device__ float g_battn[H * NB * NB];
__device__ float g_thr[H];
__device__ int   g_list[H * NB * NB];
__device__ int   g_cnt[H * NB];

// bf16 hi/lo splits
__device__ __nv_bfloat16 s_xh[S * DIM],  s_xl[S * DIM];
__device__ __nv_bfloat16 s_ah[S * DIM],  s_al[S * DIM];
__device__ __nv_bfloat16 s_wqh[DIM * DIM], s_wql[DIM * DIM];
__device__ __nv_bfloat16 s_wkh[DIM * DIM], s_wkl[DIM * DIM];
__device__ __nv_bfloat16 s_wvh[DIM * DIM], s_wvl[DIM * DIM];
__device__ __nv_bfloat16 s_woh[DIM * DIM], s_wol[DIM * DIM];

// ---------------------------------------------------------------------------
__device__ __forceinline__ uint32_t smem_u32(const void* p) {
    uint32_t a;
    asm("{ .reg .u64 t; cvta.to.shared.u64 t, %1; cvt.u32.u64 %0, t; }"
        : "=r"(a) : "l"(p));
    return a;
}
__device__ __forceinline__ void cp16(uint32_t dst, const void* src) {
    asm volatile("cp.async.cg.shared.global [%0], [%1], 16;" :: "r"(dst), "l"(src));
}
#define CP_COMMIT() asm volatile("cp.async.commit_group;" ::: "memory")
#define CP_WAIT(n)  asm volatile("cp.async.wait_group %0;" :: "n"(n) : "memory")

__device__ __forceinline__ void mma_bf16(float* c, uint32_t a0, uint32_t a1,
                                         uint32_t a2, uint32_t a3,
                                         uint32_t b0, uint32_t b1) {
    asm volatile(
        "mma.sync.aligned.m16n8k16.row.col.f32.bf16.bf16.f32 "
        "{%0,%1,%2,%3}, {%4,%5,%6,%7}, {%8,%9}, {%0,%1,%2,%3};"
        : "+f"(c[0]), "+f"(c[1]), "+f"(c[2]), "+f"(c[3])
        : "r"(a0), "r"(a1), "r"(a2), "r"(a3), "r"(b0), "r"(b1));
}

// ---------------------------------------------------------------------------
// split: fp32 -> (bf16 hi, bf16 lo)
// ---------------------------------------------------------------------------
__global__ __launch_bounds__(256) void split_kernel(
    const float* __restrict__ X, __nv_bfloat16* __restrict__ Hh,
    __nv_bfloat16* __restrict__ Hl)
{
    int i = blockIdx.x * 256 + threadIdx.x;
    float v = X[i];
    __nv_bfloat16 h = __float2bfloat16(v);
    Hh[i] = h;
    Hl[i] = __float2bfloat16(v - __bfloat162float(h));
}

// ---------------------------------------------------------------------------
// mma.sync GEMM, bf16-split 3-product: C = A W^T + bias.
// M=3072, N=K=1536. CTA 128x128, KC=64, double-buffered cp.async.
// 256 threads = 8 warps, warp tile 32m x 64n. blockIdx.z selects weight set.
// smem row = 144B = 36 u32 (64 bf16 data + pad).
// ---------------------------------------------------------------------------
#define TILEB 18432                   // 128 rows * 144B
#define STAGEB (4 * TILEB)            // Ah, Al, Wh, Wl
#define GEMM_SMEM (2 * STAGEB)        // 147456

__global__ __launch_bounds__(256, 1) void gemm_mma(
    const __nv_bfloat16* __restrict__ Ah, const __nv_bfloat16* __restrict__ Al,
    const __nv_bfloat16* __restrict__ Wh0, const __nv_bfloat16* __restrict__ Wl0,
    const __nv_bfloat16* __restrict__ Wh1, const __nv_bfloat16* __restrict__ Wl1,
    const __nv_bfloat16* __restrict__ Wh2, const __nv_bfloat16* __restrict__ Wl2,
    const float* __restrict__ b0, const float* __restrict__ b1,
    const float* __restrict__ b2,
    float* __restrict__ C0, float* __restrict__ C1, float* __restrict__ C2)
{
    extern __shared__ char smem[];
    const int z = blockIdx.z;
    const __nv_bfloat16* Wh = z == 0 ? Wh0 : (z == 1 ? Wh1 : Wh2);
    const __nv_bfloat16* Wl = z == 0 ? Wl0 : (z == 1 ? Wl1 : Wl2);
    const float* bias = z == 0 ? b0 : (z == 1 ? b1 : b2);
    float* C = z == 0 ? C0 : (z == 1 ? C1 : C2);

    const int n0 = blockIdx.x * 128;
    const int m0 = blockIdx.y * 128;
    const int tid = threadIdx.x;
    const int lane = tid & 31, wid = tid >> 5;
    const int warp_m = wid & 3, warp_n = wid >> 2;
    const int g = lane >> 2, th = lane & 3;

    const uint32_t sbase = smem_u32(smem);

    auto load_stage = [&](int stage, int c) {
        const __nv_bfloat16* srcs[4] = {
            Ah + (size_t)m0 * DIM + c * 64,
            Al + (size_t)m0 * DIM + c * 64,
            Wh + (size_t)n0 * DIM + c * 64,
            Wl + (size_t)n0 * DIM + c * 64 };
        uint32_t stb = sbase + stage * STAGEB;
#pragma unroll
        for (int t = 0; t < 4; t++) {
#pragma unroll
            for (int u = 0; u < 4; u++) {
                int f = tid + 256 * u;           // 0..1023
                int row = f >> 3, seg = f & 7;
                cp16(stb + t * TILEB + row * 144 + seg * 16,
                     srcs[t] + (size_t)row * DIM + seg * 8);
            }
        }
    };

    float acc[2][8][4];
#pragma unroll
    for (int i = 0; i < 2; i++)
#pragma unroll
        for (int j = 0; j < 8; j++)
#pragma unroll
            for (int r = 0; r < 4; r++) acc[i][j][r] = 0.f;

    load_stage(0, 0);
    CP_COMMIT();

    for (int c = 0; c < 24; c++) {
        if (c < 23) { load_stage((c + 1) & 1, c + 1); CP_COMMIT(); CP_WAIT(1); }
        else        { CP_WAIT(0); }
        __syncthreads();

        const uint32_t* AhU = (const uint32_t*)(smem + ((c & 1) * STAGEB));
        const uint32_t* AlU = AhU + TILEB / 4;
        const uint32_t* WhU = AhU + 2 * (TILEB / 4);
        const uint32_t* WlU = AhU + 3 * (TILEB / 4);

#pragma unroll
        for (int ks = 0; ks < 4; ks++) {
            uint32_t ah[2][4], al[2][4];
#pragma unroll
            for (int mt = 0; mt < 2; mt++) {
                int mrow = warp_m * 32 + mt * 16 + g;
                int bidx = mrow * 36 + ks * 8 + th;        // k16 chunk = 8 u32
                ah[mt][0] = AhU[bidx];
                ah[mt][1] = AhU[bidx + 8 * 36];
                ah[mt][2] = AhU[bidx + 4];                 // k+8 = +4 u32
                ah[mt][3] = AhU[bidx + 8 * 36 + 4];
                al[mt][0] = AlU[bidx];
                al[mt][1] = AlU[bidx + 8 * 36];
                al[mt][2] = AlU[bidx + 4];
                al[mt][3] = AlU[bidx + 8 * 36 + 4];
            }
#pragma unroll
            for (int j = 0; j < 8; j++) {
                int nrow = warp_n * 64 + j * 8 + g;
                int bidx = nrow * 36 + ks * 8 + th;
                uint32_t bh0 = WhU[bidx], bh1 = WhU[bidx + 4];
                uint32_t bl0 = WlU[bidx], bl1 = WlU[bidx + 4];
#pragma unroll
                for (int mt = 0; mt < 2; mt++) {
                    mma_bf16(acc[mt][j], ah[mt][0], ah[mt][1], ah[mt][2], ah[mt][3], bh0, bh1);
                    mma_bf16(acc[mt][j], ah[mt][0], ah[mt][1], ah[mt][2], ah[mt][3], bl0, bl1);
                    mma_bf16(acc[mt][j], al[mt][0], al[mt][1], al[mt][2], al[mt][3], bh0, bh1);
                }
            }
        }
        __syncthreads();
    }

    // epilogue: add bias, write fp32
#pragma unroll
    for (int mt = 0; mt < 2; mt++) {
        int r = m0 + warp_m * 32 + mt * 16 + g;
#pragma unroll
        for (int j = 0; j < 8; j++) {
            int col = n0 + warp_n * 64 + j * 8 + th * 2;
            float bx = bias[col], by = bias[col + 1];
            float2 o0 = { acc[mt][j][0] + bx, acc[mt][j][1] + by };
            float2 o1 = { acc[mt][j][2] + bx, acc[mt][j][3] + by };
            *(float2*)(C + (size_t)r * DIM + col) = o0;
            *(float2*)(C + (size_t)(r + 8) * DIM + col) = o1;
        }
    }
}

// ---------------------------------------------------------------------------
// RMSNorm + RoPE (unchanged)
// ---------------------------------------------------------------------------
__global__ __launch_bounds__(256) void norm_rope_kernel(
    float* __restrict__ Xq, float* __restrict__ Xk,
    const float* __restrict__ gq, const float* __restrict__ gk,
    const float* __restrict__ fc, const float* __restrict__ fs)
{
    const int s = blockIdx.x;
    float* X = blockIdx.y ? Xk : Xq;
    const float* g = blockIdx.y ? gk : gq;
    float* row = X + (size_t)s * 1536;
    const int tid = threadIdx.x;

    float ss = 0.f;
#pragma unroll
    for (int c = 0; c < 6; c++) {
        float v = row[tid + 256 * c];
        ss += v * v;
    }
#pragma unroll
    for (int o = 16; o >= 1; o >>= 1)
        ss += __shfl_xor_sync(0xffffffffu, ss, o);
    __shared__ float red[8];
    if ((tid & 31) == 0) red[tid >> 5] = ss;
    __syncthreads();
    float tot = 0.f;
#pragma unroll
    for (int w = 0; w < 8; w++) tot += red[w];
    float scale = rsqrtf(tot * (1.f / 1536.f) + 1e-5f);

#pragma unroll
    for (int u = 0; u < 3; u++) {
        int p = tid + 256 * u;
        int i = p & 63;
        float c = fc[s * 64 + i];
        float sn = fs[s * 64 + i];
        float x0 = row[2 * p] * scale * g[2 * p];
        float x1 = row[2 * p + 1] * scale * g[2 * p + 1];
        row[2 * p]     = x0 * c - x1 * sn;
        row[2 * p + 1] = x0 * sn + x1 * c;
    }
}

// ---------------------------------------------------------------------------
__global__ __launch_bounds__(256) void pool_mean(
    const float* __restrict__ Q, const float* __restrict__ Kx,
    float* __restrict__ qw, float* __restrict__ kw)
{
    const int nb = blockIdx.x;
    const float* X = blockIdx.y ? Kx : Q;
    float* Wo = blockIdx.y ? kw : qw;
    const int tid = threadIdx.x;
    float acc[6] = {0, 0, 0, 0, 0, 0};
    for (int t = 0; t < 128; t++) {
        const float* row = X + (size_t)(nb * 128 + t) * 1536;
#pragma unroll
        for (int c = 0; c < 6; c++) acc[c] += row[tid + 256 * c];
    }
#pragma unroll
    for (int c = 0; c < 6; c++)
        Wo[nb * 1536 + tid + 256 * c] = acc[c] * (1.f / 128.f);
}

// ---------------------------------------------------------------------------
__global__ void draft_scores(const float* __restrict__ qw,
                             const float* __restrict__ kw,
                             float* __restrict__ battn)
{
    const int h = blockIdx.x, l = blockIdx.y;
    const int m = threadIdx.x;
    float sc = NEG_BIG;
    if (m < 24) {
        int rl = l >> 2, cl = l & 3, rm = m >> 2, cm = m & 3;
        bool ok = (rm >= rl - 3) && (rm <= rl + 2) && (cm >= cl - 3) && (cm <= cl + 2);
        if (ok) {
            float sum = 0.f;
            const float* qr = qw + l * 1536 + h * 128;
            const float* kr = kw + m * 1536 + h * 128;
#pragma unroll 8
            for (int d = 0; d < 128; d++) sum += qr[d] * kr[d];
            sc = sum * SCALE;
        }
    }
    float mx = sc;
#pragma unroll
    for (int o = 16; o >= 1; o >>= 1)
        mx = fmaxf(mx, __shfl_xor_sync(0xffffffffu, mx, o));
    float e = __expf(sc - mx);
    float se = e;
#pragma unroll
    for (int o = 16; o >= 1; o >>= 1)
        se += __shfl_xor_sync(0xffffffffu, se, o);
    if (m < 24) battn[(h * 24 + l) * 24 + m] = e / se;
}

// ---------------------------------------------------------------------------
__global__ void topk_thresh(const float* __restrict__ battn, float* __restrict__ thr)
{
    const int h = blockIdx.x;
    __shared__ float buf[576];
    __shared__ float result;
    for (int e = threadIdx.x; e < 576; e += 256) buf[e] = battn[h * 576 + e];
    if (threadIdx.x == 0) result = 0.f;
    __syncthreads();
    for (int e = threadIdx.x; e < 576; e += 256) {
        float v = buf[e];
        int cg = 0, ce = 0;
        for (int x = 0; x < 576; x++) {
            cg += (buf[x] > v);
            ce += (buf[x] == v);
        }
        if (cg <= 128 && cg + ce >= 129) result = v;
    }
    __syncthreads();
    if (threadIdx.x == 0) thr[h] = result;
}

// ---------------------------------------------------------------------------
__global__ void build_lists(const float* __restrict__ battn,
                            const float* __restrict__ thr,
                            int* __restrict__ list, int* __restrict__ cnt)
{
    const int l = blockIdx.x, h = blockIdx.y;
    const int m = threadIdx.x;
    bool sel = (m < 24) && (battn[(h * 24 + l) * 24 + m] > thr[h]);
    unsigned msk = __ballot_sync(0xffffffffu, sel);
    int pos = __popc(msk & ((1u << m) - 1u));
    if (sel) list[(h * 24 + l) * 24 + pos] = m;
    if (m == 0) cnt[h * 24 + l] = __popc(msk);
}

// ---------------------------------------------------------------------------
// Block-sparse flash attention (scalar FFMA; unchanged, proven correct)
// ---------------------------------------------------------------------------
#define ATT_SMEM (3 * 128 * 129 * 4)

__global__ __launch_bounds__(256, 1) void attn_sparse(
    const float* __restrict__ Qg, const float* __restrict__ Kg,
    const float* __restrict__ Vg, const int* __restrict__ list,
    const int* __restrict__ cnt, float* __restrict__ O)
{
    extern __shared__ float sm[];
    float* Qs = sm;
    float* Ks = sm + 128 * 129;
    float* Vs = sm + 2 * 128 * 129;

    const int l = blockIdx.x, h = blockIdx.y;
    const int tid = threadIdx.x;
    const int tx = tid & 15;
    const int ty = tid >> 4;

#pragma unroll
    for (int u = 0; u < 16; u++) {
        int f = tid + 256 * u;
        int r = f >> 5;
        int d4 = (f & 31) << 2;
        float4 v = *(const float4*)(Qg + (size_t)(l * 128 + r) * 1536 + h * 128 + d4);
        Qs[r * 129 + d4 + 0] = v.x; Qs[r * 129 + d4 + 1] = v.y;
        Qs[r * 129 + d4 + 2] = v.z; Qs[r * 129 + d4 + 3] = v.w;
    }

    float accO[8][8];
    float mrow[8], drow[8];
#pragma unroll
    for (int i = 0; i < 8; i++) {
        mrow[i] = NEG_BIG;
        drow[i] = 0.f;
#pragma unroll
        for (int j = 0; j < 8; j++) accO[i][j] = 0.f;
    }

    const int nc = cnt[h * 24 + l];
    for (int b = 0; b < nc; b++) {
        const int mb = list[(h * 24 + l) * 24 + b];
        __syncthreads();
#pragma unroll
        for (int u = 0; u < 16; u++) {
            int f = tid + 256 * u;
            int r = f >> 5;
            int d4 = (f & 31) << 2;
            float4 vk = *(const float4*)(Kg + (size_t)(mb * 128 + r) * 1536 + h * 128 + d4);
            Ks[r * 129 + d4 + 0] = vk.x; Ks[r * 129 + d4 + 1] = vk.y;
            Ks[r * 129 + d4 + 2] = vk.z; Ks[r * 129 + d4 + 3] = vk.w;
            float4 vv = *(const float4*)(Vg + (size_t)(mb * 128 + r) * 1536 + h * 128 + d4);
            Vs[r * 129 + d4 + 0] = vv.x; Vs[r * 129 + d4 + 1] = vv.y;
            Vs[r * 129 + d4 + 2] = vv.z; Vs[r * 129 + d4 + 3] = vv.w;
        }
        __syncthreads();

        float s[8][8];
#pragma unroll
        for (int i = 0; i < 8; i++)
#pragma unroll
            for (int j = 0; j < 8; j++) s[i][j] = 0.f;
        for (int d = 0; d < 128; d++) {
            float a[8], bb[8];
#pragma unroll
            for (int i = 0; i < 8; i++) a[i] = Qs[(ty + 16 * i) * 129 + d];
#pragma unroll
            for (int j = 0; j < 8; j++) bb[j] = Ks[(tx + 16 * j) * 129 + d];
#pragma unroll
            for (int i = 0; i < 8; i++)
#pragma unroll
                for (int j = 0; j < 8; j++) s[i][j] += a[i] * bb[j];
        }

        float fac[8];
#pragma unroll
        for (int i = 0; i < 8; i++) {
            float rmax = NEG_BIG;
#pragma unroll
            for (int j = 0; j < 8; j++) {
                s[i][j] *= SCALE;
                rmax = fmaxf(rmax, s[i][j]);
            }
#pragma unroll
            for (int o = 8; o >= 1; o >>= 1)
                rmax = fmaxf(rmax, __shfl_xor_sync(0xffffffffu, rmax, o));
            float newm = fmaxf(mrow[i], rmax);
            fac[i] = __expf(mrow[i] - newm);
            float rs = 0.f;
#pragma unroll
            for (int j = 0; j < 8; j++) {
                s[i][j] = __expf(s[i][j] - newm);
                rs += s[i][j];
            }
#pragma unroll
            for (int o = 8; o >= 1; o >>= 1)
                rs += __shfl_xor_sync(0xffffffffu, rs, o);
            drow[i] = drow[i] * fac[i] + rs;
            mrow[i] = newm;
#pragma unroll
            for (int j = 0; j < 8; j++) accO[i][j] *= fac[i];
        }

        __syncthreads();
#pragma unroll
        for (int i = 0; i < 8; i++)
#pragma unroll
            for (int j = 0; j < 8; j++)
                Ks[(ty + 16 * i) * 129 + tx + 16 * j] = s[i][j];
        __syncthreads();

        for (int t = 0; t < 128; t++) {
            float a[8], bb[8];
#pragma unroll
            for (int i = 0; i < 8; i++) a[i] = Ks[(ty + 16 * i) * 129 + t];
#pragma unroll
            for (int j = 0; j < 8; j++) bb[j] = Vs[t * 129 + tx + 16 * j];
#pragma unroll
            for (int i = 0; i < 8; i++)
#pragma unroll
                for (int j = 0; j < 8; j++) accO[i][j] += a[i] * bb[j];
        }
    }

#pragma unroll
    for (int i = 0; i < 8; i++) {
        float inv = drow[i] > 0.f ? 1.f / drow[i] : 0.f;
        int row = l * 128 + ty + 16 * i;
#pragma unroll
        for (int j = 0; j < 8; j++)
            O[(size_t)row * 1536 + h * 128 + tx + 16 * j] = accO[i][j] * inv;
    }
}

// ---------------------------------------------------------------------------
extern "C" void kernel_launch(void* const* d_in, const int* in_sizes, int n_in,
                              void* d_out, int out_size)
{
    const float* x  = (const float*)d_in[0];
    const float* wq = (const float*)d_in[1];
    const float* bq = (const float*)d_in[2];
    const float* wk = (const float*)d_in[3];
    const float* bk = (const float*)d_in[4];
    const float* wv = (const float*)d_in[5];
    const float* bv = (const float*)d_in[6];
    const float* wo = (const float*)d_in[7];
    const float* bo = (const float*)d_in[8];
    const float* gq = (const float*)d_in[9];
    const float* gk = (const float*)d_in[10];
    const float* fc = (const float*)d_in[11];
    const float* fs = (const float*)d_in[12];
    float* out = (float*)d_out;

    float *qp, *kp, *vp, *ap, *qwp, *kwp, *bap, *thp;
    int *lp, *cp;
    cudaGetSymbolAddress((void**)&qp, g_q);
    cudaGetSymbolAddress((void**)&kp, g_k);
    cudaGetSymbolAddress((void**)&vp, g_v);
    cudaGetSymbolAddress((void**)&ap, g_att);
    cudaGetSymbolAddress((void**)&qwp, g_qw);
    cudaGetSymbolAddress((void**)&kwp, g_kw);
    cudaGetSymbolAddress((void**)&bap, g_battn);
    cudaGetSymbolAddress((void**)&thp, g_thr);
    cudaGetSymbolAddress((void**)&lp, g_list);
    cudaGetSymbolAddress((void**)&cp, g_cnt);

    __nv_bfloat16 *xh, *xl, *ah, *al;
    __nv_bfloat16 *wqh, *wql, *wkh, *wkl, *wvh, *wvl, *woh, *wol;
    cudaGetSymbolAddress((void**)&xh, s_xh);
    cudaGetSymbolAddress((void**)&xl, s_xl);
    cudaGetSymbolAddress((void**)&ah, s_ah);
    cudaGetSymbolAddress((void**)&al, s_al);
    cudaGetSymbolAddress((void**)&wqh, s_wqh);
    cudaGetSymbolAddress((void**)&wql, s_wql);
    cudaGetSymbolAddress((void**)&wkh, s_wkh);
    cudaGetSymbolAddress((void**)&wkl, s_wkl);
    cudaGetSymbolAddress((void**)&wvh, s_wvh);
    cudaGetSymbolAddress((void**)&wvl, s_wvl);
    cudaGetSymbolAddress((void**)&woh, s_woh);
    cudaGetSymbolAddress((void**)&wol, s_wol);

    cudaFuncSetAttribute(attn_sparse, cudaFuncAttributeMaxDynamicSharedMemorySize, ATT_SMEM);
    cudaFuncSetAttribute(gemm_mma, cudaFuncAttributeMaxDynamicSharedMemorySize, GEMM_SMEM);

    // splits
    split_kernel<<<(S * DIM) / 256, 256>>>(x, xh, xl);
    split_kernel<<<(DIM * DIM) / 256, 256>>>(wq, wqh, wql);
    split_kernel<<<(DIM * DIM) / 256, 256>>>(wk, wkh, wkl);
    split_kernel<<<(DIM * DIM) / 256, 256>>>(wv, wvh, wvl);
    split_kernel<<<(DIM * DIM) / 256, 256>>>(wo, woh, wol);

    // Q/K/V projections (z-batched)
    gemm_mma<<<dim3(12, 24, 3), 256, GEMM_SMEM>>>(
        xh, xl, wqh, wql, wkh, wkl, wvh, wvl, bq, bk, bv, qp, kp, vp);

    norm_rope_kernel<<<dim3(S, 2), 256>>>(qp, kp, gq, gk, fc, fs);
    pool_mean<<<dim3(NB, 2), 256>>>(qp, kp, qwp, kwp);
    draft_scores<<<dim3(H, NB), 32>>>(qwp, kwp, bap);
    topk_thresh<<<H, 256>>>(bap, thp);
    build_lists<<<dim3(NB, H), 32>>>(bap, thp, lp, cp);

    attn_sparse<<<dim3(NB, H), 256, ATT_SMEM>>>(qp, kp, vp, lp, cp, ap);

    // O projection
    split_kernel<<<(S * DIM) / 256, 256>>>(ap, ah, al);
    gemm_mma<<<dim3(12, 24, 1), 256, GEMM_SMEM>>>(
        ah, al, woh, wol, woh, wol, woh, wol, bo, bo, bo, out, out, out);
}

// round 7
// speedup vs baseline: 4.3114x; 1.6464x over previous
#include <cuda_runtime.h>
#include <cuda_bf16.h>
#include <cstdint>

#define S 3072
#define DIM 1536
#define H 12
#define NB 24
#define SCALE 0.08838834764831845f   // 1/sqrt(128)
#define NEG_BIG (-1e30f)

// ---------------- scratch (device globals; no allocation allowed) ----------
__device__ float g_q[S * DIM];
__device__ float g_k[S * DIM];
__device__ float g_v[S * DIM];
__device__ float g_att[S * DIM];
__device__ float g_qw[NB * DIM];
__device__ float g_kw[NB * DIM];
__device__ float g_battn[H * NB * NB];
__device__ float g_thr[H];
__device__ int   g_list[H * NB * NB];
__device__ int   g_cnt[H * NB];

// bf16 hi/lo splits
__device__ __nv_bfloat16 s_xh[S * DIM],  s_xl[S * DIM];
__device__ __nv_bfloat16 s_ah[S * DIM],  s_al[S * DIM];
__device__ __nv_bfloat16 s_wqh[DIM * DIM], s_wql[DIM * DIM];
__device__ __nv_bfloat16 s_wkh[DIM * DIM], s_wkl[DIM * DIM];
__device__ __nv_bfloat16 s_wvh[DIM * DIM], s_wvl[DIM * DIM];
__device__ __nv_bfloat16 s_woh[DIM * DIM], s_wol[DIM * DIM];
// attention operand splits
__device__ __nv_bfloat16 s_qh[S * DIM], s_ql[S * DIM];
__device__ __nv_bfloat16 s_kh[S * DIM], s_kl[S * DIM];
__device__ __nv_bfloat16 s_vth[DIM * S], s_vtl[DIM * S];   // transposed [d][t]

// ---------------------------------------------------------------------------
__device__ __forceinline__ uint32_t smem_u32(const void* p) {
    uint32_t a;
    asm("{ .reg .u64 t; cvta.to.shared.u64 t, %1; cvt.u32.u64 %0, t; }"
        : "=r"(a) : "l"(p));
    return a;
}
__device__ __forceinline__ void cp16(uint32_t dst, const void* src) {
    asm volatile("cp.async.cg.shared.global [%0], [%1], 16;" :: "r"(dst), "l"(src));
}
#define CP_COMMIT() asm volatile("cp.async.commit_group;" ::: "memory")
#define CP_WAIT(n)  asm volatile("cp.async.wait_group %0;" :: "n"(n) : "memory")

__device__ __forceinline__ void mma_bf16(float* c, uint32_t a0, uint32_t a1,
                                         uint32_t a2, uint32_t a3,
                                         uint32_t b0, uint32_t b1) {
    asm volatile(
        "mma.sync.aligned.m16n8k16.row.col.f32.bf16.bf16.f32 "
        "{%0,%1,%2,%3}, {%4,%5,%6,%7}, {%8,%9}, {%0,%1,%2,%3};"
        : "+f"(c[0]), "+f"(c[1]), "+f"(c[2]), "+f"(c[3])
        : "r"(a0), "r"(a1), "r"(a2), "r"(a3), "r"(b0), "r"(b1));
}
__device__ __forceinline__ uint32_t pack2(float x, float y) {
    __nv_bfloat162 t = __floats2bfloat162_rn(x, y);
    return *(uint32_t*)&t;
}

// ---------------------------------------------------------------------------
// split: fp32 -> (bf16 hi, bf16 lo)
// ---------------------------------------------------------------------------
__global__ __launch_bounds__(256) void split_kernel(
    const float* __restrict__ X, __nv_bfloat16* __restrict__ Hh,
    __nv_bfloat16* __restrict__ Hl)
{
    int i = blockIdx.x * 256 + threadIdx.x;
    float v = X[i];
    __nv_bfloat16 h = __float2bfloat16(v);
    Hh[i] = h;
    Hl[i] = __float2bfloat16(v - __bfloat162float(h));
}

// ---------------------------------------------------------------------------
// transpose + split: V[t][d] fp32 -> Vt_hi/lo[d][t] bf16
// ---------------------------------------------------------------------------
__global__ __launch_bounds__(256) void vt_split(
    const float* __restrict__ V, __nv_bfloat16* __restrict__ Th,
    __nv_bfloat16* __restrict__ Tl)
{
    __shared__ float tile[32][33];
    const int t0 = blockIdx.x * 32, d0 = blockIdx.y * 32;
    const int tx = threadIdx.x & 31, ty = threadIdx.x >> 5;   // 32 x 8
#pragma unroll
    for (int i = 0; i < 4; i++)
        tile[ty + 8 * i][tx] = V[(size_t)(t0 + ty + 8 * i) * DIM + d0 + tx];
    __syncthreads();
#pragma unroll
    for (int i = 0; i < 4; i++) {
        float v = tile[tx][ty + 8 * i];
        __nv_bfloat16 h = __float2bfloat16(v);
        size_t o = (size_t)(d0 + ty + 8 * i) * S + t0 + tx;
        Th[o] = h;
        Tl[o] = __float2bfloat16(v - __bfloat162float(h));
    }
}

// ---------------------------------------------------------------------------
// mma.sync GEMM, bf16-split 3-product: C = A W^T + bias.  (proven R4)
// ---------------------------------------------------------------------------
#define TILEB 18432                   // 128 rows * 144B
#define STAGEB (4 * TILEB)
#define GEMM_SMEM (2 * STAGEB)

__global__ __launch_bounds__(256, 1) void gemm_mma(
    const __nv_bfloat16* __restrict__ Ah, const __nv_bfloat16* __restrict__ Al,
    const __nv_bfloat16* __restrict__ Wh0, const __nv_bfloat16* __restrict__ Wl0,
    const __nv_bfloat16* __restrict__ Wh1, const __nv_bfloat16* __restrict__ Wl1,
    const __nv_bfloat16* __restrict__ Wh2, const __nv_bfloat16* __restrict__ Wl2,
    const float* __restrict__ b0, const float* __restrict__ b1,
    const float* __restrict__ b2,
    float* __restrict__ C0, float* __restrict__ C1, float* __restrict__ C2)
{
    extern __shared__ char smem[];
    const int z = blockIdx.z;
    const __nv_bfloat16* Wh = z == 0 ? Wh0 : (z == 1 ? Wh1 : Wh2);
    const __nv_bfloat16* Wl = z == 0 ? Wl0 : (z == 1 ? Wl1 : Wl2);
    const float* bias = z == 0 ? b0 : (z == 1 ? b1 : b2);
    float* C = z == 0 ? C0 : (z == 1 ? C1 : C2);

    const int n0 = blockIdx.x * 128;
    const int m0 = blockIdx.y * 128;
    const int tid = threadIdx.x;
    const int lane = tid & 31, wid = tid >> 5;
    const int warp_m = wid & 3, warp_n = wid >> 2;
    const int g = lane >> 2, th = lane & 3;

    const uint32_t sbase = smem_u32(smem);

    auto load_stage = [&](int stage, int c) {
        const __nv_bfloat16* srcs[4] = {
            Ah + (size_t)m0 * DIM + c * 64,
            Al + (size_t)m0 * DIM + c * 64,
            Wh + (size_t)n0 * DIM + c * 64,
            Wl + (size_t)n0 * DIM + c * 64 };
        uint32_t stb = sbase + stage * STAGEB;
#pragma unroll
        for (int t = 0; t < 4; t++) {
#pragma unroll
            for (int u = 0; u < 4; u++) {
                int f = tid + 256 * u;
                int row = f >> 3, seg = f & 7;
                cp16(stb + t * TILEB + row * 144 + seg * 16,
                     srcs[t] + (size_t)row * DIM + seg * 8);
            }
        }
    };

    float acc[2][8][4];
#pragma unroll
    for (int i = 0; i < 2; i++)
#pragma unroll
        for (int j = 0; j < 8; j++)
#pragma unroll
            for (int r = 0; r < 4; r++) acc[i][j][r] = 0.f;

    load_stage(0, 0);
    CP_COMMIT();

    for (int c = 0; c < 24; c++) {
        if (c < 23) { load_stage((c + 1) & 1, c + 1); CP_COMMIT(); CP_WAIT(1); }
        else        { CP_WAIT(0); }
        __syncthreads();

        const uint32_t* AhU = (const uint32_t*)(smem + ((c & 1) * STAGEB));
        const uint32_t* AlU = AhU + TILEB / 4;
        const uint32_t* WhU = AhU + 2 * (TILEB / 4);
        const uint32_t* WlU = AhU + 3 * (TILEB / 4);

#pragma unroll
        for (int ks = 0; ks < 4; ks++) {
            uint32_t ah[2][4], al[2][4];
#pragma unroll
            for (int mt = 0; mt < 2; mt++) {
                int mrow = warp_m * 32 + mt * 16 + g;
                int bidx = mrow * 36 + ks * 8 + th;
                ah[mt][0] = AhU[bidx];
                ah[mt][1] = AhU[bidx + 8 * 36];
                ah[mt][2] = AhU[bidx + 4];
                ah[mt][3] = AhU[bidx + 8 * 36 + 4];
                al[mt][0] = AlU[bidx];
                al[mt][1] = AlU[bidx + 8 * 36];
                al[mt][2] = AlU[bidx + 4];
                al[mt][3] = AlU[bidx + 8 * 36 + 4];
            }
#pragma unroll
            for (int j = 0; j < 8; j++) {
                int nrow = warp_n * 64 + j * 8 + g;
                int bidx = nrow * 36 + ks * 8 + th;
                uint32_t bh0 = WhU[bidx], bh1 = WhU[bidx + 4];
                uint32_t bl0 = WlU[bidx], bl1 = WlU[bidx + 4];
#pragma unroll
                for (int mt = 0; mt < 2; mt++) {
                    mma_bf16(acc[mt][j], ah[mt][0], ah[mt][1], ah[mt][2], ah[mt][3], bh0, bh1);
                    mma_bf16(acc[mt][j], ah[mt][0], ah[mt][1], ah[mt][2], ah[mt][3], bl0, bl1);
                    mma_bf16(acc[mt][j], al[mt][0], al[mt][1], al[mt][2], al[mt][3], bh0, bh1);
                }
            }
        }
        __syncthreads();
    }

#pragma unroll
    for (int mt = 0; mt < 2; mt++) {
        int r = m0 + warp_m * 32 + mt * 16 + g;
#pragma unroll
        for (int j = 0; j < 8; j++) {
            int col = n0 + warp_n * 64 + j * 8 + th * 2;
            float bx = bias[col], by = bias[col + 1];
            float2 o0 = { acc[mt][j][0] + bx, acc[mt][j][1] + by };
            float2 o1 = { acc[mt][j][2] + bx, acc[mt][j][3] + by };
            *(float2*)(C + (size_t)r * DIM + col) = o0;
            *(float2*)(C + (size_t)(r + 8) * DIM + col) = o1;
        }
    }
}

// ---------------------------------------------------------------------------
// RMSNorm + RoPE
// ---------------------------------------------------------------------------
__global__ __launch_bounds__(256) void norm_rope_kernel(
    float* __restrict__ Xq, float* __restrict__ Xk,
    const float* __restrict__ gq, const float* __restrict__ gk,
    const float* __restrict__ fc, const float* __restrict__ fs)
{
    const int s = blockIdx.x;
    float* X = blockIdx.y ? Xk : Xq;
    const float* g = blockIdx.y ? gk : gq;
    float* row = X + (size_t)s * 1536;
    const int tid = threadIdx.x;

    float ss = 0.f;
#pragma unroll
    for (int c = 0; c < 6; c++) {
        float v = row[tid + 256 * c];
        ss += v * v;
    }
#pragma unroll
    for (int o = 16; o >= 1; o >>= 1)
        ss += __shfl_xor_sync(0xffffffffu, ss, o);
    __shared__ float red[8];
    if ((tid & 31) == 0) red[tid >> 5] = ss;
    __syncthreads();
    float tot = 0.f;
#pragma unroll
    for (int w = 0; w < 8; w++) tot += red[w];
    float scale = rsqrtf(tot * (1.f / 1536.f) + 1e-5f);

#pragma unroll
    for (int u = 0; u < 3; u++) {
        int p = tid + 256 * u;
        int i = p & 63;
        float c = fc[s * 64 + i];
        float sn = fs[s * 64 + i];
        float x0 = row[2 * p] * scale * g[2 * p];
        float x1 = row[2 * p + 1] * scale * g[2 * p + 1];
        row[2 * p]     = x0 * c - x1 * sn;
        row[2 * p + 1] = x0 * sn + x1 * c;
    }
}

// ---------------------------------------------------------------------------
__global__ __launch_bounds__(256) void pool_mean(
    const float* __restrict__ Q, const float* __restrict__ Kx,
    float* __restrict__ qw, float* __restrict__ kw)
{
    const int nb = blockIdx.x;
    const float* X = blockIdx.y ? Kx : Q;
    float* Wo = blockIdx.y ? kw : qw;
    const int tid = threadIdx.x;
    float acc[6] = {0, 0, 0, 0, 0, 0};
    for (int t = 0; t < 128; t++) {
        const float* row = X + (size_t)(nb * 128 + t) * 1536;
#pragma unroll
        for (int c = 0; c < 6; c++) acc[c] += row[tid + 256 * c];
    }
#pragma unroll
    for (int c = 0; c < 6; c++)
        Wo[nb * 1536 + tid + 256 * c] = acc[c] * (1.f / 128.f);
}

// ---------------------------------------------------------------------------
__global__ void draft_scores(const float* __restrict__ qw,
                             const float* __restrict__ kw,
                             float* __restrict__ battn)
{
    const int h = blockIdx.x, l = blockIdx.y;
    const int m = threadIdx.x;
    float sc = NEG_BIG;
    if (m < 24) {
        int rl = l >> 2, cl = l & 3, rm = m >> 2, cm = m & 3;
        bool ok = (rm >= rl - 3) && (rm <= rl + 2) && (cm >= cl - 3) && (cm <= cl + 2);
        if (ok) {
            float sum = 0.f;
            const float* qr = qw + l * 1536 + h * 128;
            const float* kr = kw + m * 1536 + h * 128;
#pragma unroll 8
            for (int d = 0; d < 128; d++) sum += qr[d] * kr[d];
            sc = sum * SCALE;
        }
    }
    float mx = sc;
#pragma unroll
    for (int o = 16; o >= 1; o >>= 1)
        mx = fmaxf(mx, __shfl_xor_sync(0xffffffffu, mx, o));
    float e = __expf(sc - mx);
    float se = e;
#pragma unroll
    for (int o = 16; o >= 1; o >>= 1)
        se += __shfl_xor_sync(0xffffffffu, se, o);
    if (m < 24) battn[(h * 24 + l) * 24 + m] = e / se;
}

// ---------------------------------------------------------------------------
__global__ void topk_thresh(const float* __restrict__ battn, float* __restrict__ thr)
{
    const int h = blockIdx.x;
    __shared__ float buf[576];
    __shared__ float result;
    for (int e = threadIdx.x; e < 576; e += 256) buf[e] = battn[h * 576 + e];
    if (threadIdx.x == 0) result = 0.f;
    __syncthreads();
    for (int e = threadIdx.x; e < 576; e += 256) {
        float v = buf[e];
        int cg = 0, ce = 0;
        for (int x = 0; x < 576; x++) {
            cg += (buf[x] > v);
            ce += (buf[x] == v);
        }
        if (cg <= 128 && cg + ce >= 129) result = v;
    }
    __syncthreads();
    if (threadIdx.x == 0) thr[h] = result;
}

// ---------------------------------------------------------------------------
__global__ void build_lists(const float* __restrict__ battn,
                            const float* __restrict__ thr,
                            int* __restrict__ list, int* __restrict__ cnt)
{
    const int l = blockIdx.x, h = blockIdx.y;
    const int m = threadIdx.x;
    bool sel = (m < 24) && (battn[(h * 24 + l) * 24 + m] > thr[h]);
    unsigned msk = __ballot_sync(0xffffffffu, sel);
    int pos = __popc(msk & ((1u << m) - 1u));
    if (sel) list[(h * 24 + l) * 24 + pos] = m;
    if (m == 0) cnt[h * 24 + l] = __popc(msk);
}

// ---------------------------------------------------------------------------
// Block-sparse flash attention via mma.sync, bf16-split 3-product.
// grid (NB, H), 256 thr = 8 warps; warp owns 16 query rows.
// smem: Qh,Ql,Kh,Kl,Vth,Vtl tiles, 272B row stride (conflict-free frags).
// P stays in registers (S-accum frag layout == PV A-frag layout).
// ---------------------------------------------------------------------------
#define AT_U32 68
#define AT_TILEB (128 * AT_U32 * 4)     // 34816
#define ATT_SMEM (6 * AT_TILEB)         // 208896

__global__ __launch_bounds__(256, 1) void attn_mma(
    const __nv_bfloat16* __restrict__ Qh, const __nv_bfloat16* __restrict__ Ql,
    const __nv_bfloat16* __restrict__ Kh, const __nv_bfloat16* __restrict__ Kl,
    const __nv_bfloat16* __restrict__ Vth, const __nv_bfloat16* __restrict__ Vtl,
    const int* __restrict__ list, const int* __restrict__ cnt,
    float* __restrict__ O)
{
    extern __shared__ char smem[];
    const int l = blockIdx.x, h = blockIdx.y;
    const int tid = threadIdx.x;
    const int lane = tid & 31, wid = tid >> 5;
    const int g = lane >> 2, th = lane & 3;
    const uint32_t sb = smem_u32(smem);

    // load Q hi/lo once
#pragma unroll
    for (int t = 0; t < 2; t++) {
        const __nv_bfloat16* src = t ? Ql : Qh;
        uint32_t dst = sb + t * AT_TILEB;
#pragma unroll
        for (int u = 0; u < 8; u++) {
            int f = tid + 256 * u;
            int row = f >> 4, seg = f & 15;
            cp16(dst + row * 272 + seg * 16,
                 src + (size_t)(l * 128 + row) * DIM + h * 128 + seg * 8);
        }
    }
    CP_COMMIT();

    float oacc[16][4];
#pragma unroll
    for (int j = 0; j < 16; j++)
        oacc[j][0] = oacc[j][1] = oacc[j][2] = oacc[j][3] = 0.f;
    float m0 = NEG_BIG, m1 = NEG_BIG, den0 = 0.f, den1 = 0.f;

    const uint32_t* QhU = (const uint32_t*)smem;
    const uint32_t* QlU = QhU + AT_TILEB / 4;
    const uint32_t* KhU = QhU + 2 * (AT_TILEB / 4);
    const uint32_t* KlU = QhU + 3 * (AT_TILEB / 4);
    const uint32_t* VhU = QhU + 4 * (AT_TILEB / 4);
    const uint32_t* VlU = QhU + 5 * (AT_TILEB / 4);

    const int nc = cnt[h * 24 + l];
    for (int b = 0; b < nc; b++) {
        const int mb = list[(h * 24 + l) * 24 + b];
        __syncthreads();                 // prior reads of K/V smem done
#pragma unroll
        for (int u = 0; u < 8; u++) {
            int f = tid + 256 * u;
            int row = f >> 4, seg = f & 15;
            size_t ko = (size_t)(mb * 128 + row) * DIM + h * 128 + seg * 8;
            size_t vo = (size_t)(h * 128 + row) * S + mb * 128 + seg * 8;
            uint32_t so = row * 272 + seg * 16;
            cp16(sb + 2 * AT_TILEB + so, Kh + ko);
            cp16(sb + 3 * AT_TILEB + so, Kl + ko);
            cp16(sb + 4 * AT_TILEB + so, Vth + vo);
            cp16(sb + 5 * AT_TILEB + so, Vtl + vo);
        }
        CP_COMMIT();
        CP_WAIT(0);
        __syncthreads();

        // ---- S = Q K^T (3-product split) ----
        float sacc[16][4];
#pragma unroll
        for (int j = 0; j < 16; j++)
            sacc[j][0] = sacc[j][1] = sacc[j][2] = sacc[j][3] = 0.f;
#pragma unroll
        for (int ks = 0; ks < 8; ks++) {
            int aidx = (wid * 16 + g) * AT_U32 + ks * 8 + th;
            uint32_t ah0 = QhU[aidx], ah1 = QhU[aidx + 8 * AT_U32];
            uint32_t ah2 = QhU[aidx + 4], ah3 = QhU[aidx + 8 * AT_U32 + 4];
            uint32_t al0 = QlU[aidx], al1 = QlU[aidx + 8 * AT_U32];
            uint32_t al2 = QlU[aidx + 4], al3 = QlU[aidx + 8 * AT_U32 + 4];
#pragma unroll
            for (int j = 0; j < 16; j++) {
                int bidx = (j * 8 + g) * AT_U32 + ks * 8 + th;
                uint32_t bh0 = KhU[bidx], bh1 = KhU[bidx + 4];
                uint32_t bl0 = KlU[bidx], bl1 = KlU[bidx + 4];
                mma_bf16(sacc[j], ah0, ah1, ah2, ah3, bh0, bh1);
                mma_bf16(sacc[j], ah0, ah1, ah2, ah3, bl0, bl1);
                mma_bf16(sacc[j], al0, al1, al2, al3, bh0, bh1);
            }
        }

        // ---- online softmax (rows g and g+8; reduce over th lanes) ----
        float mx0 = NEG_BIG, mx1 = NEG_BIG;
#pragma unroll
        for (int j = 0; j < 16; j++) {
            sacc[j][0] *= SCALE; sacc[j][1] *= SCALE;
            sacc[j][2] *= SCALE; sacc[j][3] *= SCALE;
            mx0 = fmaxf(mx0, fmaxf(sacc[j][0], sacc[j][1]));
            mx1 = fmaxf(mx1, fmaxf(sacc[j][2], sacc[j][3]));
        }
        mx0 = fmaxf(mx0, __shfl_xor_sync(0xffffffffu, mx0, 1));
        mx0 = fmaxf(mx0, __shfl_xor_sync(0xffffffffu, mx0, 2));
        mx1 = fmaxf(mx1, __shfl_xor_sync(0xffffffffu, mx1, 1));
        mx1 = fmaxf(mx1, __shfl_xor_sync(0xffffffffu, mx1, 2));
        float nm0 = fmaxf(m0, mx0), nm1 = fmaxf(m1, mx1);
        float f0 = __expf(m0 - nm0), f1 = __expf(m1 - nm1);
        float rs0 = 0.f, rs1 = 0.f;
#pragma unroll
        for (int j = 0; j < 16; j++) {
            sacc[j][0] = __expf(sacc[j][0] - nm0);
            sacc[j][1] = __expf(sacc[j][1] - nm0);
            sacc[j][2] = __expf(sacc[j][2] - nm1);
            sacc[j][3] = __expf(sacc[j][3] - nm1);
            rs0 += sacc[j][0] + sacc[j][1];
            rs1 += sacc[j][2] + sacc[j][3];
        }
        rs0 += __shfl_xor_sync(0xffffffffu, rs0, 1);
        rs0 += __shfl_xor_sync(0xffffffffu, rs0, 2);
        rs1 += __shfl_xor_sync(0xffffffffu, rs1, 1);
        rs1 += __shfl_xor_sync(0xffffffffu, rs1, 2);
        den0 = den0 * f0 + rs0; m0 = nm0;
        den1 = den1 * f1 + rs1; m1 = nm1;
#pragma unroll
        for (int j = 0; j < 16; j++) {
            oacc[j][0] *= f0; oacc[j][1] *= f0;
            oacc[j][2] *= f1; oacc[j][3] *= f1;
        }

        // ---- O += P V (P from registers, hi/lo split) ----
#pragma unroll
        for (int kk = 0; kk < 8; kk++) {
            float p00 = sacc[2 * kk][0],     p01 = sacc[2 * kk][1];
            float p10 = sacc[2 * kk][2],     p11 = sacc[2 * kk][3];
            float p20 = sacc[2 * kk + 1][0], p21 = sacc[2 * kk + 1][1];
            float p30 = sacc[2 * kk + 1][2], p31 = sacc[2 * kk + 1][3];
            uint32_t ph0 = pack2(p00, p01), ph1 = pack2(p10, p11);
            uint32_t ph2 = pack2(p20, p21), ph3 = pack2(p30, p31);
            __nv_bfloat162 h0 = *(__nv_bfloat162*)&ph0;
            __nv_bfloat162 h1 = *(__nv_bfloat162*)&ph1;
            __nv_bfloat162 h2 = *(__nv_bfloat162*)&ph2;
            __nv_bfloat162 h3 = *(__nv_bfloat162*)&ph3;
            uint32_t pl0 = pack2(p00 - __bfloat162float(h0.x), p01 - __bfloat162float(h0.y));
            uint32_t pl1 = pack2(p10 - __bfloat162float(h1.x), p11 - __bfloat162float(h1.y));
            uint32_t pl2 = pack2(p20 - __bfloat162float(h2.x), p21 - __bfloat162float(h2.y));
            uint32_t pl3 = pack2(p30 - __bfloat162float(h3.x), p31 - __bfloat162float(h3.y));
#pragma unroll
            for (int j = 0; j < 16; j++) {
                int bidx = (j * 8 + g) * AT_U32 + kk * 8 + th;
                uint32_t vh0 = VhU[bidx], vh1 = VhU[bidx + 4];
                uint32_t vl0 = VlU[bidx], vl1 = VlU[bidx + 4];
                mma_bf16(oacc[j], ph0, ph1, ph2, ph3, vh0, vh1);
                mma_bf16(oacc[j], ph0, ph1, ph2, ph3, vl0, vl1);
                mma_bf16(oacc[j], pl0, pl1, pl2, pl3, vh0, vh1);
            }
        }
    }

    // epilogue
    float inv0 = den0 > 0.f ? 1.f / den0 : 0.f;
    float inv1 = den1 > 0.f ? 1.f / den1 : 0.f;
    const int r0 = l * 128 + wid * 16 + g, r1 = r0 + 8;
#pragma unroll
    for (int j = 0; j < 16; j++) {
        int col = h * 128 + j * 8 + 2 * th;
        float2 w0 = { oacc[j][0] * inv0, oacc[j][1] * inv0 };
        float2 w1 = { oacc[j][2] * inv1, oacc[j][3] * inv1 };
        *(float2*)(O + (size_t)r0 * DIM + col) = w0;
        *(float2*)(O + (size_t)r1 * DIM + col) = w1;
    }
}

// ---------------------------------------------------------------------------
extern "C" void kernel_launch(void* const* d_in, const int* in_sizes, int n_in,
                              void* d_out, int out_size)
{
    const float* x  = (const float*)d_in[0];
    const float* wq = (const float*)d_in[1];
    const float* bq = (const float*)d_in[2];
    const float* wk = (const float*)d_in[3];
    const float* bk = (const float*)d_in[4];
    const float* wv = (const float*)d_in[5];
    const float* bv = (const float*)d_in[6];
    const float* wo = (const float*)d_in[7];
    const float* bo = (const float*)d_in[8];
    const float* gq = (const float*)d_in[9];
    const float* gk = (const float*)d_in[10];
    const float* fc = (const float*)d_in[11];
    const float* fs = (const float*)d_in[12];
    float* out = (float*)d_out;

    float *qp, *kp, *vp, *ap, *qwp, *kwp, *bap, *thp;
    int *lp, *cp;
    cudaGetSymbolAddress((void**)&qp, g_q);
    cudaGetSymbolAddress((void**)&kp, g_k);
    cudaGetSymbolAddress((void**)&vp, g_v);
    cudaGetSymbolAddress((void**)&ap, g_att);
    cudaGetSymbolAddress((void**)&qwp, g_qw);
    cudaGetSymbolAddress((void**)&kwp, g_kw);
    cudaGetSymbolAddress((void**)&bap, g_battn);
    cudaGetSymbolAddress((void**)&thp, g_thr);
    cudaGetSymbolAddress((void**)&lp, g_list);
    cudaGetSymbolAddress((void**)&cp, g_cnt);

    __nv_bfloat16 *xh, *xl, *ah, *al;
    __nv_bfloat16 *wqh, *wql, *wkh, *wkl, *wvh, *wvl, *woh, *wol;
    __nv_bfloat16 *qh, *ql, *kh, *kl, *vth, *vtl;
    cudaGetSymbolAddress((void**)&xh, s_xh);
    cudaGetSymbolAddress((void**)&xl, s_xl);
    cudaGetSymbolAddress((void**)&ah, s_ah);
    cudaGetSymbolAddress((void**)&al, s_al);
    cudaGetSymbolAddress((void**)&wqh, s_wqh);
    cudaGetSymbolAddress((void**)&wql, s_wql);
    cudaGetSymbolAddress((void**)&wkh, s_wkh);
    cudaGetSymbolAddress((void**)&wkl, s_wkl);
    cudaGetSymbolAddress((void**)&wvh, s_wvh);
    cudaGetSymbolAddress((void**)&wvl, s_wvl);
    cudaGetSymbolAddress((void**)&woh, s_woh);
    cudaGetSymbolAddress((void**)&wol, s_wol);
    cudaGetSymbolAddress((void**)&qh, s_qh);
    cudaGetSymbolAddress((void**)&ql, s_ql);
    cudaGetSymbolAddress((void**)&kh, s_kh);
    cudaGetSymbolAddress((void**)&kl, s_kl);
    cudaGetSymbolAddress((void**)&vth, s_vth);
    cudaGetSymbolAddress((void**)&vtl, s_vtl);

    cudaFuncSetAttribute(gemm_mma, cudaFuncAttributeMaxDynamicSharedMemorySize, GEMM_SMEM);
    cudaFuncSetAttribute(attn_mma, cudaFuncAttributeMaxDynamicSharedMemorySize, ATT_SMEM);

    // splits
    split_kernel<<<(S * DIM) / 256, 256>>>(x, xh, xl);
    split_kernel<<<(DIM * DIM) / 256, 256>>>(wq, wqh, wql);
    split_kernel<<<(DIM * DIM) / 256, 256>>>(wk, wkh, wkl);
    split_kernel<<<(DIM * DIM) / 256, 256>>>(wv, wvh, wvl);
    split_kernel<<<(DIM * DIM) / 256, 256>>>(wo, woh, wol);

    // Q/K/V projections (z-batched)
    gemm_mma<<<dim3(12, 24, 3), 256, GEMM_SMEM>>>(
        xh, xl, wqh, wql, wkh, wkl, wvh, wvl, bq, bk, bv, qp, kp, vp);

    norm_rope_kernel<<<dim3(S, 2), 256>>>(qp, kp, gq, gk, fc, fs);
    pool_mean<<<dim3(NB, 2), 256>>>(qp, kp, qwp, kwp);
    draft_scores<<<dim3(H, NB), 32>>>(qwp, kwp, bap);
    topk_thresh<<<H, 256>>>(bap, thp);
    build_lists<<<dim3(NB, H), 32>>>(bap, thp, lp, cp);

    // attention operand splits
    split_kernel<<<(S * DIM) / 256, 256>>>(qp, qh, ql);
    split_kernel<<<(S * DIM) / 256, 256>>>(kp, kh, kl);
    vt_split<<<dim3(S / 32, DIM / 32), 256>>>(vp, vth, vtl);

    attn_mma<<<dim3(NB, H), 256, ATT_SMEM>>>(qh, ql, kh, kl, vth, vtl, lp, cp, ap);

    // O projection
    split_kernel<<<(S * DIM) / 256, 256>>>(ap, ah, al);
    gemm_mma<<<dim3(12, 24, 1), 256, GEMM_SMEM>>>(
        ah, al, woh, wol, woh, wol, woh, wol, bo, bo, bo, out, out, out);
}

// round 10
// speedup vs baseline: 4.7659x; 1.1054x over previous
#include <cuda_runtime.h>
#include <cuda_bf16.h>
#include <cstdint>

#define S 3072
#define DIM 1536
#define H 12
#define NB 24
#define SCALE 0.08838834764831845f   // 1/sqrt(128)
#define NEG_BIG (-1e30f)

// ---------------- scratch (device globals; no allocation allowed) ----------
__device__ float g_q[S * DIM];
__device__ float g_k[S * DIM];
__device__ float g_v[S * DIM];
__device__ float g_qw[NB * DIM];
__device__ float g_kw[NB * DIM];
__device__ float g_battn[H * NB * NB];
__device__ float g_thr[H];
__device__ int   g_list[H * NB * NB];
__device__ int   g_cnt[H * NB];
__device__ int   g_order[H * NB];

// bf16 hi/lo splits
__device__ __nv_bfloat16 s_xh[S * DIM],  s_xl[S * DIM];
__device__ __nv_bfloat16 s_ah[S * DIM],  s_al[S * DIM];
__device__ __nv_bfloat16 s_wqh[DIM * DIM], s_wql[DIM * DIM];
__device__ __nv_bfloat16 s_wkh[DIM * DIM], s_wkl[DIM * DIM];
__device__ __nv_bfloat16 s_wvh[DIM * DIM], s_wvl[DIM * DIM];
__device__ __nv_bfloat16 s_woh[DIM * DIM], s_wol[DIM * DIM];
// attention operand splits
__device__ __nv_bfloat16 s_qh[S * DIM], s_ql[S * DIM];
__device__ __nv_bfloat16 s_kh[S * DIM], s_kl[S * DIM];
__device__ __nv_bfloat16 s_vth[DIM * S], s_vtl[DIM * S];   // transposed [d][t]

// ---------------------------------------------------------------------------
__device__ __forceinline__ uint32_t smem_u32(const void* p) {
    uint32_t a;
    asm("{ .reg .u64 t; cvta.to.shared.u64 t, %1; cvt.u32.u64 %0, t; }"
        : "=r"(a) : "l"(p));
    return a;
}
__device__ __forceinline__ void cp16(uint32_t dst, const void* src) {
    asm volatile("cp.async.cg.shared.global [%0], [%1], 16;" :: "r"(dst), "l"(src));
}
#define CP_COMMIT() asm volatile("cp.async.commit_group;" ::: "memory")
#define CP_WAIT(n)  asm volatile("cp.async.wait_group %0;" :: "n"(n) : "memory")

__device__ __forceinline__ void mma_bf16(float* c, uint32_t a0, uint32_t a1,
                                         uint32_t a2, uint32_t a3,
                                         uint32_t b0, uint32_t b1) {
    asm volatile(
        "mma.sync.aligned.m16n8k16.row.col.f32.bf16.bf16.f32 "
        "{%0,%1,%2,%3}, {%4,%5,%6,%7}, {%8,%9}, {%0,%1,%2,%3};"
        : "+f"(c[0]), "+f"(c[1]), "+f"(c[2]), "+f"(c[3])
        : "r"(a0), "r"(a1), "r"(a2), "r"(a3), "r"(b0), "r"(b1));
}
__device__ __forceinline__ uint32_t pack2(float x, float y) {
    __nv_bfloat162 t = __floats2bfloat162_rn(x, y);
    return *(uint32_t*)&t;
}

// ---------------------------------------------------------------------------
// split: fp32 -> (bf16 hi, bf16 lo)
// ---------------------------------------------------------------------------
__global__ __launch_bounds__(256) void split_kernel(
    const float* __restrict__ X, __nv_bfloat16* __restrict__ Hh,
    __nv_bfloat16* __restrict__ Hl)
{
    int i = blockIdx.x * 256 + threadIdx.x;
    float v = X[i];
    __nv_bfloat16 h = __float2bfloat16(v);
    Hh[i] = h;
    Hl[i] = __float2bfloat16(v - __bfloat162float(h));
}

// ---------------------------------------------------------------------------
// transpose + split: V[t][d] fp32 -> Vt_hi/lo[d][t] bf16
// ---------------------------------------------------------------------------
__global__ __launch_bounds__(256) void vt_split(
    const float* __restrict__ V, __nv_bfloat16* __restrict__ Th,
    __nv_bfloat16* __restrict__ Tl)
{
    __shared__ float tile[32][33];
    const int t0 = blockIdx.x * 32, d0 = blockIdx.y * 32;
    const int tx = threadIdx.x & 31, ty = threadIdx.x >> 5;   // 32 x 8
#pragma unroll
    for (int i = 0; i < 4; i++)
        tile[ty + 8 * i][tx] = V[(size_t)(t0 + ty + 8 * i) * DIM + d0 + tx];
    __syncthreads();
#pragma unroll
    for (int i = 0; i < 4; i++) {
        float v = tile[tx][ty + 8 * i];
        __nv_bfloat16 h = __float2bfloat16(v);
        size_t o = (size_t)(d0 + ty + 8 * i) * S + t0 + tx;
        Th[o] = h;
        Tl[o] = __float2bfloat16(v - __bfloat162float(h));
    }
}

// ---------------------------------------------------------------------------
// mma.sync GEMM, bf16-split 3-product: C = A W^T + bias.  3-stage pipeline.
// ---------------------------------------------------------------------------
#define TILEB 18432                   // 128 rows * 144B
#define STAGEB (4 * TILEB)
#define GEMM_SMEM (3 * STAGEB)        // 221184

__global__ __launch_bounds__(256, 1) void gemm_mma(
    const __nv_bfloat16* __restrict__ Ah, const __nv_bfloat16* __restrict__ Al,
    const __nv_bfloat16* __restrict__ Wh0, const __nv_bfloat16* __restrict__ Wl0,
    const __nv_bfloat16* __restrict__ Wh1, const __nv_bfloat16* __restrict__ Wl1,
    const __nv_bfloat16* __restrict__ Wh2, const __nv_bfloat16* __restrict__ Wl2,
    const float* __restrict__ b0, const float* __restrict__ b1,
    const float* __restrict__ b2,
    float* __restrict__ C0, float* __restrict__ C1, float* __restrict__ C2)
{
    extern __shared__ char smem[];
    const int z = blockIdx.z;
    const __nv_bfloat16* Wh = z == 0 ? Wh0 : (z == 1 ? Wh1 : Wh2);
    const __nv_bfloat16* Wl = z == 0 ? Wl0 : (z == 1 ? Wl1 : Wl2);
    const float* bias = z == 0 ? b0 : (z == 1 ? b1 : b2);
    float* C = z == 0 ? C0 : (z == 1 ? C1 : C2);

    const int n0 = blockIdx.x * 128;
    const int m0 = blockIdx.y * 128;
    const int tid = threadIdx.x;
    const int lane = tid & 31, wid = tid >> 5;
    const int warp_m = wid & 3, warp_n = wid >> 2;
    const int g = lane >> 2, th = lane & 3;

    const uint32_t sbase = smem_u32(smem);

    auto load_stage = [&](int stage, int c) {
        const __nv_bfloat16* srcs[4] = {
            Ah + (size_t)m0 * DIM + c * 64,
            Al + (size_t)m0 * DIM + c * 64,
            Wh + (size_t)n0 * DIM + c * 64,
            Wl + (size_t)n0 * DIM + c * 64 };
        uint32_t stb = sbase + stage * STAGEB;
#pragma unroll
        for (int t = 0; t < 4; t++) {
#pragma unroll
            for (int u = 0; u < 4; u++) {
                int f = tid + 256 * u;
                int row = f >> 3, seg = f & 7;
                cp16(stb + t * TILEB + row * 144 + seg * 16,
                     srcs[t] + (size_t)row * DIM + seg * 8);
            }
        }
    };

    float acc[2][8][4];
#pragma unroll
    for (int i = 0; i < 2; i++)
#pragma unroll
        for (int j = 0; j < 8; j++)
#pragma unroll
            for (int r = 0; r < 4; r++) acc[i][j][r] = 0.f;

    load_stage(0, 0); CP_COMMIT();
    load_stage(1, 1); CP_COMMIT();

    for (int c = 0; c < 24; c++) {
        if (c < 23) { CP_WAIT(1); } else { CP_WAIT(0); }
        __syncthreads();

        const uint32_t* AhU = (const uint32_t*)(smem + ((c % 3) * STAGEB));
        const uint32_t* AlU = AhU + TILEB / 4;
        const uint32_t* WhU = AhU + 2 * (TILEB / 4);
        const uint32_t* WlU = AhU + 3 * (TILEB / 4);

#pragma unroll
        for (int ks = 0; ks < 4; ks++) {
            uint32_t ah[2][4], al[2][4];
#pragma unroll
            for (int mt = 0; mt < 2; mt++) {
                int mrow = warp_m * 32 + mt * 16 + g;
                int bidx = mrow * 36 + ks * 8 + th;
                ah[mt][0] = AhU[bidx];
                ah[mt][1] = AhU[bidx + 8 * 36];
                ah[mt][2] = AhU[bidx + 4];
                ah[mt][3] = AhU[bidx + 8 * 36 + 4];
                al[mt][0] = AlU[bidx];
                al[mt][1] = AlU[bidx + 8 * 36];
                al[mt][2] = AlU[bidx + 4];
                al[mt][3] = AlU[bidx + 8 * 36 + 4];
            }
#pragma unroll
            for (int j = 0; j < 8; j++) {
                int nrow = warp_n * 64 + j * 8 + g;
                int bidx = nrow * 36 + ks * 8 + th;
                uint32_t bh0 = WhU[bidx], bh1 = WhU[bidx + 4];
                uint32_t bl0 = WlU[bidx], bl1 = WlU[bidx + 4];
#pragma unroll
                for (int mt = 0; mt < 2; mt++) {
                    mma_bf16(acc[mt][j], ah[mt][0], ah[mt][1], ah[mt][2], ah[mt][3], bh0, bh1);
                    mma_bf16(acc[mt][j], ah[mt][0], ah[mt][1], ah[mt][2], ah[mt][3], bl0, bl1);
                    mma_bf16(acc[mt][j], al[mt][0], al[mt][1], al[mt][2], al[mt][3], bh0, bh1);
                }
            }
        }
        if (c + 2 < 24) { load_stage((c + 2) % 3, c + 2); CP_COMMIT(); }
        __syncthreads();
    }

#pragma unroll
    for (int mt = 0; mt < 2; mt++) {
        int r = m0 + warp_m * 32 + mt * 16 + g;
#pragma unroll
        for (int j = 0; j < 8; j++) {
            int col = n0 + warp_n * 64 + j * 8 + th * 2;
            float bx = bias[col], by = bias[col + 1];
            float2 o0 = { acc[mt][j][0] + bx, acc[mt][j][1] + by };
            float2 o1 = { acc[mt][j][2] + bx, acc[mt][j][3] + by };
            *(float2*)(C + (size_t)r * DIM + col) = o0;
            *(float2*)(C + (size_t)(r + 8) * DIM + col) = o1;
        }
    }
}

// ---------------------------------------------------------------------------
// RMSNorm + RoPE, fused bf16 hi/lo split output (fp32 kept for pooling)
// ---------------------------------------------------------------------------
__global__ __launch_bounds__(256) void norm_rope_kernel(
    float* __restrict__ Xq, float* __restrict__ Xk,
    __nv_bfloat16* __restrict__ Qh, __nv_bfloat16* __restrict__ Ql,
    __nv_bfloat16* __restrict__ Kh, __nv_bfloat16* __restrict__ Kl,
    const float* __restrict__ gq, const float* __restrict__ gk,
    const float* __restrict__ fc, const float* __restrict__ fs)
{
    const int s = blockIdx.x;
    float* X = blockIdx.y ? Xk : Xq;
    __nv_bfloat16* Oh = blockIdx.y ? Kh : Qh;
    __nv_bfloat16* Ol = blockIdx.y ? Kl : Ql;
    const float* g = blockIdx.y ? gk : gq;
    float* row = X + (size_t)s * 1536;
    const int tid = threadIdx.x;

    float ss = 0.f;
#pragma unroll
    for (int c = 0; c < 6; c++) {
        float v = row[tid + 256 * c];
        ss += v * v;
    }
#pragma unroll
    for (int o = 16; o >= 1; o >>= 1)
        ss += __shfl_xor_sync(0xffffffffu, ss, o);
    __shared__ float red[8];
    if ((tid & 31) == 0) red[tid >> 5] = ss;
    __syncthreads();
    float tot = 0.f;
#pragma unroll
    for (int w = 0; w < 8; w++) tot += red[w];
    float scale = rsqrtf(tot * (1.f / 1536.f) + 1e-5f);

#pragma unroll
    for (int u = 0; u < 3; u++) {
        int p = tid + 256 * u;
        int i = p & 63;
        float c = fc[s * 64 + i];
        float sn = fs[s * 64 + i];
        float x0 = row[2 * p] * scale * g[2 * p];
        float x1 = row[2 * p + 1] * scale * g[2 * p + 1];
        float y0 = x0 * c - x1 * sn;
        float y1 = x0 * sn + x1 * c;
        row[2 * p]     = y0;
        row[2 * p + 1] = y1;
        size_t o = (size_t)s * 1536 + 2 * p;
        __nv_bfloat16 h0 = __float2bfloat16(y0);
        __nv_bfloat16 h1 = __float2bfloat16(y1);
        Oh[o] = h0;     Oh[o + 1] = h1;
        Ol[o] = __float2bfloat16(y0 - __bfloat162float(h0));
        Ol[o + 1] = __float2bfloat16(y1 - __bfloat162float(h1));
    }
}

// ---------------------------------------------------------------------------
__global__ __launch_bounds__(256) void pool_mean(
    const float* __restrict__ Q, const float* __restrict__ Kx,
    float* __restrict__ qw, float* __restrict__ kw)
{
    const int nb = blockIdx.x;
    const float* X = blockIdx.y ? Kx : Q;
    float* Wo = blockIdx.y ? kw : qw;
    const int tid = threadIdx.x;
    float acc[6] = {0, 0, 0, 0, 0, 0};
    for (int t = 0; t < 128; t++) {
        const float* row = X + (size_t)(nb * 128 + t) * 1536;
#pragma unroll
        for (int c = 0; c < 6; c++) acc[c] += row[tid + 256 * c];
    }
#pragma unroll
    for (int c = 0; c < 6; c++)
        Wo[nb * 1536 + tid + 256 * c] = acc[c] * (1.f / 128.f);
}

// ---------------------------------------------------------------------------
__global__ void draft_scores(const float* __restrict__ qw,
                             const float* __restrict__ kw,
                             float* __restrict__ battn)
{
    const int h = blockIdx.x, l = blockIdx.y;
    const int m = threadIdx.x;
    float sc = NEG_BIG;
    if (m < 24) {
        int rl = l >> 2, cl = l & 3, rm = m >> 2, cm = m & 3;
        bool ok = (rm >= rl - 3) && (rm <= rl + 2) && (cm >= cl - 3) && (cm <= cl + 2);
        if (ok) {
            float sum = 0.f;
            const float* qr = qw + l * 1536 + h * 128;
            const float* kr = kw + m * 1536 + h * 128;
#pragma unroll 8
            for (int d = 0; d < 128; d++) sum += qr[d] * kr[d];
            sc = sum * SCALE;
        }
    }
    float mx = sc;
#pragma unroll
    for (int o = 16; o >= 1; o >>= 1)
        mx = fmaxf(mx, __shfl_xor_sync(0xffffffffu, mx, o));
    float e = __expf(sc - mx);
    float se = e;
#pragma unroll
    for (int o = 16; o >= 1; o >>= 1)
        se += __shfl_xor_sync(0xffffffffu, se, o);
    if (m < 24) battn[(h * 24 + l) * 24 + m] = e / se;
}

// ---------------------------------------------------------------------------
__global__ void topk_thresh(const float* __restrict__ battn, float* __restrict__ thr)
{
    const int h = blockIdx.x;
    __shared__ float buf[576];
    __shared__ float result;
    for (int e = threadIdx.x; e < 576; e += 256) buf[e] = battn[h * 576 + e];
    if (threadIdx.x == 0) result = 0.f;
    __syncthreads();
    for (int e = threadIdx.x; e < 576; e += 256) {
        float v = buf[e];
        int cg = 0, ce = 0;
        for (int x = 0; x < 576; x++) {
            cg += (buf[x] > v);
            ce += (buf[x] == v);
        }
        if (cg <= 128 && cg + ce >= 129) result = v;
    }
    __syncthreads();
    if (threadIdx.x == 0) thr[h] = result;
}

// ---------------------------------------------------------------------------
__global__ void build_lists(const float* __restrict__ battn,
                            const float* __restrict__ thr,
                            int* __restrict__ list, int* __restrict__ cnt)
{
    const int l = blockIdx.x, h = blockIdx.y;
    const int m = threadIdx.x;
    bool sel = (m < 24) && (battn[(h * 24 + l) * 24 + m] > thr[h]);
    unsigned msk = __ballot_sync(0xffffffffu, sel);
    int pos = __popc(msk & ((1u << m) - 1u));
    if (sel) list[(h * 24 + l) * 24 + pos] = m;
    if (m == 0) cnt[h * 24 + l] = __popc(msk);
}

// ---------------------------------------------------------------------------
// LPT ordering: counting-sort the 288 pairs by descending block count.
// ---------------------------------------------------------------------------
__global__ void order_pairs(const int* __restrict__ cnt, int* __restrict__ order)
{
    __shared__ int bucket[32];
    __shared__ int base[32];
    const int tid = threadIdx.x;          // 288 threads, one per pair
    if (tid < 32) bucket[tid] = 0;
    __syncthreads();
    int nc = cnt[tid];
    atomicAdd(&bucket[nc], 1);
    __syncthreads();
    if (tid == 0) {
        int acc = 0;
        for (int v = 31; v >= 0; v--) { base[v] = acc; acc += bucket[v]; }
    }
    __syncthreads();
    int pos = atomicAdd(&base[nc], 1);
    order[pos] = tid;
}

// ---------------------------------------------------------------------------
// Block-sparse flash attention via mma.sync (R7), LPT pair order,
// epilogue writes bf16 hi/lo split directly.
// ---------------------------------------------------------------------------
#define AT_U32 68
#define AT_TILEB (128 * AT_U32 * 4)     // 34816
#define ATT_SMEM (6 * AT_TILEB)         // 208896

__global__ __launch_bounds__(256, 1) void attn_mma(
    const __nv_bfloat16* __restrict__ Qh, const __nv_bfloat16* __restrict__ Ql,
    const __nv_bfloat16* __restrict__ Kh, const __nv_bfloat16* __restrict__ Kl,
    const __nv_bfloat16* __restrict__ Vth, const __nv_bfloat16* __restrict__ Vtl,
    const int* __restrict__ list, const int* __restrict__ cnt,
    const int* __restrict__ order,
    __nv_bfloat16* __restrict__ OAh, __nv_bfloat16* __restrict__ OAl)
{
    extern __shared__ char smem[];
    const int pair = order[blockIdx.x];
    const int h = pair / 24, l = pair % 24;
    const int tid = threadIdx.x;
    const int lane = tid & 31, wid = tid >> 5;
    const int g = lane >> 2, th = lane & 3;
    const uint32_t sb = smem_u32(smem);

    // load Q hi/lo once
#pragma unroll
    for (int t = 0; t < 2; t++) {
        const __nv_bfloat16* src = t ? Ql : Qh;
        uint32_t dst = sb + t * AT_TILEB;
#pragma unroll
        for (int u = 0; u < 8; u++) {
            int f = tid + 256 * u;
            int row = f >> 4, seg = f & 15;
            cp16(dst + row * 272 + seg * 16,
                 src + (size_t)(l * 128 + row) * DIM + h * 128 + seg * 8);
        }
    }
    CP_COMMIT();

    float oacc[16][4];
#pragma unroll
    for (int j = 0; j < 16; j++)
        oacc[j][0] = oacc[j][1] = oacc[j][2] = oacc[j][3] = 0.f;
    float m0 = NEG_BIG, m1 = NEG_BIG, den0 = 0.f, den1 = 0.f;

    const uint32_t* QhU = (const uint32_t*)smem;
    const uint32_t* QlU = QhU + AT_TILEB / 4;
    const uint32_t* KhU = QhU + 2 * (AT_TILEB / 4);
    const uint32_t* KlU = QhU + 3 * (AT_TILEB / 4);
    const uint32_t* VhU = QhU + 4 * (AT_TILEB / 4);
    const uint32_t* VlU = QhU + 5 * (AT_TILEB / 4);

    const int nc = cnt[pair];
    for (int b = 0; b < nc; b++) {
        const int mb = list[pair * 24 + b];
        __syncthreads();
#pragma unroll
        for (int u = 0; u < 8; u++) {
            int f = tid + 256 * u;
            int row = f >> 4, seg = f & 15;
            size_t ko = (size_t)(mb * 128 + row) * DIM + h * 128 + seg * 8;
            size_t vo = (size_t)(h * 128 + row) * S + mb * 128 + seg * 8;
            uint32_t so = row * 272 + seg * 16;
            cp16(sb + 2 * AT_TILEB + so, Kh + ko);
            cp16(sb + 3 * AT_TILEB + so, Kl + ko);
            cp16(sb + 4 * AT_TILEB + so, Vth + vo);
            cp16(sb + 5 * AT_TILEB + so, Vtl + vo);
        }
        CP_COMMIT();
        CP_WAIT(0);
        __syncthreads();

        // ---- S = Q K^T (3-product split) ----
        float sacc[16][4];
#pragma unroll
        for (int j = 0; j < 16; j++)
            sacc[j][0] = sacc[j][1] = sacc[j][2] = sacc[j][3] = 0.f;
#pragma unroll
        for (int ks = 0; ks < 8; ks++) {
            int aidx = (wid * 16 + g) * AT_U32 + ks * 8 + th;
            uint32_t ah0 = QhU[aidx], ah1 = QhU[aidx + 8 * AT_U32];
            uint32_t ah2 = QhU[aidx + 4], ah3 = QhU[aidx + 8 * AT_U32 + 4];
            uint32_t al0 = QlU[aidx], al1 = QlU[aidx + 8 * AT_U32];
            uint32_t al2 = QlU[aidx + 4], al3 = QlU[aidx + 8 * AT_U32 + 4];
#pragma unroll
            for (int j = 0; j < 16; j++) {
                int bidx = (j * 8 + g) * AT_U32 + ks * 8 + th;
                uint32_t bh0 = KhU[bidx], bh1 = KhU[bidx + 4];
                uint32_t bl0 = KlU[bidx], bl1 = KlU[bidx + 4];
                mma_bf16(sacc[j], ah0, ah1, ah2, ah3, bh0, bh1);
                mma_bf16(sacc[j], ah0, ah1, ah2, ah3, bl0, bl1);
                mma_bf16(sacc[j], al0, al1, al2, al3, bh0, bh1);
            }
        }

        // ---- online softmax ----
        float mx0 = NEG_BIG, mx1 = NEG_BIG;
#pragma unroll
        for (int j = 0; j < 16; j++) {
            sacc[j][0] *= SCALE; sacc[j][1] *= SCALE;
            sacc[j][2] *= SCALE; sacc[j][3] *= SCALE;
            mx0 = fmaxf(mx0, fmaxf(sacc[j][0], sacc[j][1]));
            mx1 = fmaxf(mx1, fmaxf(sacc[j][2], sacc[j][3]));
        }
        mx0 = fmaxf(mx0, __shfl_xor_sync(0xffffffffu, mx0, 1));
        mx0 = fmaxf(mx0, __shfl_xor_sync(0xffffffffu, mx0, 2));
        mx1 = fmaxf(mx1, __shfl_xor_sync(0xffffffffu, mx1, 1));
        mx1 = fmaxf(mx1, __shfl_xor_sync(0xffffffffu, mx1, 2));
        float nm0 = fmaxf(m0, mx0), nm1 = fmaxf(m1, mx1);
        float f0 = __expf(m0 - nm0), f1 = __expf(m1 - nm1);
        float rs0 = 0.f, rs1 = 0.f;
#pragma unroll
        for (int j = 0; j < 16; j++) {
            sacc[j][0] = __expf(sacc[j][0] - nm0);
            sacc[j][1] = __expf(sacc[j][1] - nm0);
            sacc[j][2] = __expf(sacc[j][2] - nm1);
            sacc[j][3] = __expf(sacc[j][3] - nm1);
            rs0 += sacc[j][0] + sacc[j][1];
            rs1 += sacc[j][2] + sacc[j][3];
        }
        rs0 += __shfl_xor_sync(0xffffffffu, rs0, 1);
        rs0 += __shfl_xor_sync(0xffffffffu, rs0, 2);
        rs1 += __shfl_xor_sync(0xffffffffu, rs1, 1);
        rs1 += __shfl_xor_sync(0xffffffffu, rs1, 2);
        den0 = den0 * f0 + rs0; m0 = nm0;
        den1 = den1 * f1 + rs1; m1 = nm1;
#pragma unroll
        for (int j = 0; j < 16; j++) {
            oacc[j][0] *= f0; oacc[j][1] *= f0;
            oacc[j][2] *= f1; oacc[j][3] *= f1;
        }

        // ---- O += P V (P from registers, hi/lo split) ----
#pragma unroll
        for (int kk = 0; kk < 8; kk++) {
            float p00 = sacc[2 * kk][0],     p01 = sacc[2 * kk][1];
            float p10 = sacc[2 * kk][2],     p11 = sacc[2 * kk][3];
            float p20 = sacc[2 * kk + 1][0], p21 = sacc[2 * kk + 1][1];
            float p30 = sacc[2 * kk + 1][2], p31 = sacc[2 * kk + 1][3];
            uint32_t ph0 = pack2(p00, p01), ph1 = pack2(p10, p11);
            uint32_t ph2 = pack2(p20, p21), ph3 = pack2(p30, p31);
            __nv_bfloat162 h0 = *(__nv_bfloat162*)&ph0;
            __nv_bfloat162 h1 = *(__nv_bfloat162*)&ph1;
            __nv_bfloat162 h2 = *(__nv_bfloat162*)&ph2;
            __nv_bfloat162 h3 = *(__nv_bfloat162*)&ph3;
            uint32_t pl0 = pack2(p00 - __bfloat162float(h0.x), p01 - __bfloat162float(h0.y));
            uint32_t pl1 = pack2(p10 - __bfloat162float(h1.x), p11 - __bfloat162float(h1.y));
            uint32_t pl2 = pack2(p20 - __bfloat162float(h2.x), p21 - __bfloat162float(h2.y));
            uint32_t pl3 = pack2(p30 - __bfloat162float(h3.x), p31 - __bfloat162float(h3.y));
#pragma unroll
            for (int j = 0; j < 16; j++) {
                int bidx = (j * 8 + g) * AT_U32 + kk * 8 + th;
                uint32_t vh0 = VhU[bidx], vh1 = VhU[bidx + 4];
                uint32_t vl0 = VlU[bidx], vl1 = VlU[bidx + 4];
                mma_bf16(oacc[j], ph0, ph1, ph2, ph3, vh0, vh1);
                mma_bf16(oacc[j], ph0, ph1, ph2, ph3, vl0, vl1);
                mma_bf16(oacc[j], pl0, pl1, pl2, pl3, vh0, vh1);
            }
        }
    }

    // epilogue: normalize + bf16 hi/lo split write
    float inv0 = den0 > 0.f ? 1.f / den0 : 0.f;
    float inv1 = den1 > 0.f ? 1.f / den1 : 0.f;
    const int r0 = l * 128 + wid * 16 + g, r1 = r0 + 8;
#pragma unroll
    for (int j = 0; j < 16; j++) {
        int col = h * 128 + j * 8 + 2 * th;
        float v00 = oacc[j][0] * inv0, v01 = oacc[j][1] * inv0;
        float v10 = oacc[j][2] * inv1, v11 = oacc[j][3] * inv1;
        uint32_t h0 = pack2(v00, v01);
        uint32_t h1 = pack2(v10, v11);
        __nv_bfloat162 b0 = *(__nv_bfloat162*)&h0;
        __nv_bfloat162 b1 = *(__nv_bfloat162*)&h1;
        uint32_t l0 = pack2(v00 - __bfloat162float(b0.x), v01 - __bfloat162float(b0.y));
        uint32_t l1 = pack2(v10 - __bfloat162float(b1.x), v11 - __bfloat162float(b1.y));
        *(uint32_t*)(OAh + (size_t)r0 * DIM + col) = h0;
        *(uint32_t*)(OAl + (size_t)r0 * DIM + col) = l0;
        *(uint32_t*)(OAh + (size_t)r1 * DIM + col) = h1;
        *(uint32_t*)(OAl + (size_t)r1 * DIM + col) = l1;
    }
}

// ---------------------------------------------------------------------------
extern "C" void kernel_launch(void* const* d_in, const int* in_sizes, int n_in,
                              void* d_out, int out_size)
{
    const float* x  = (const float*)d_in[0];
    const float* wq = (const float*)d_in[1];
    const float* bq = (const float*)d_in[2];
    const float* wk = (const float*)d_in[3];
    const float* bk = (const float*)d_in[4];
    const float* wv = (const float*)d_in[5];
    const float* bv = (const float*)d_in[6];
    const float* wo = (const float*)d_in[7];
    const float* bo = (const float*)d_in[8];
    const float* gq = (const float*)d_in[9];
    const float* gk = (const float*)d_in[10];
    const float* fc = (const float*)d_in[11];
    const float* fs = (const float*)d_in[12];
    float* out = (float*)d_out;

    float *qp, *kp, *vp, *qwp, *kwp, *bap, *thp;
    int *lp, *cp, *op;
    cudaGetSymbolAddress((void**)&qp, g_q);
    cudaGetSymbolAddress((void**)&kp, g_k);
    cudaGetSymbolAddress((void**)&vp, g_v);
    cudaGetSymbolAddress((void**)&qwp, g_qw);
    cudaGetSymbolAddress((void**)&kwp, g_kw);
    cudaGetSymbolAddress((void**)&bap, g_battn);
    cudaGetSymbolAddress((void**)&thp, g_thr);
    cudaGetSymbolAddress((void**)&lp, g_list);
    cudaGetSymbolAddress((void**)&cp, g_cnt);
    cudaGetSymbolAddress((void**)&op, g_order);

    __nv_bfloat16 *xh, *xl, *ah, *al;
    __nv_bfloat16 *wqh, *wql, *wkh, *wkl, *wvh, *wvl, *woh, *wol;
    __nv_bfloat16 *qh, *ql, *kh, *kl, *vth, *vtl;
    cudaGetSymbolAddress((void**)&xh, s_xh);
    cudaGetSymbolAddress((void**)&xl, s_xl);
    cudaGetSymbolAddress((void**)&ah, s_ah);
    cudaGetSymbolAddress((void**)&al, s_al);
    cudaGetSymbolAddress((void**)&wqh, s_wqh);
    cudaGetSymbolAddress((void**)&wql, s_wql);
    cudaGetSymbolAddress((void**)&wkh, s_wkh);
    cudaGetSymbolAddress((void**)&wkl, s_wkl);
    cudaGetSymbolAddress((void**)&wvh, s_wvh);
    cudaGetSymbolAddress((void**)&wvl, s_wvl);
    cudaGetSymbolAddress((void**)&woh, s_woh);
    cudaGetSymbolAddress((void**)&wol, s_wol);
    cudaGetSymbolAddress((void**)&qh, s_qh);
    cudaGetSymbolAddress((void**)&ql, s_ql);
    cudaGetSymbolAddress((void**)&kh, s_kh);
    cudaGetSymbolAddress((void**)&kl, s_kl);
    cudaGetSymbolAddress((void**)&vth, s_vth);
    cudaGetSymbolAddress((void**)&vtl, s_vtl);

    cudaFuncSetAttribute(gemm_mma, cudaFuncAttributeMaxDynamicSharedMemorySize, GEMM_SMEM);
    cudaFuncSetAttribute(attn_mma, cudaFuncAttributeMaxDynamicSharedMemorySize, ATT_SMEM);

    // splits (x + weights)
    split_kernel<<<(S * DIM) / 256, 256>>>(x, xh, xl);
    split_kernel<<<(DIM * DIM) / 256, 256>>>(wq, wqh, wql);
    split_kernel<<<(DIM * DIM) / 256, 256>>>(wk, wkh, wkl);
    split_kernel<<<(DIM * DIM) / 256, 256>>>(wv, wvh, wvl);
    split_kernel<<<(DIM * DIM) / 256, 256>>>(wo, woh, wol);

    // Q/K/V projections (z-batched)
    gemm_mma<<<dim3(12, 24, 3), 256, GEMM_SMEM>>>(
        xh, xl, wqh, wql, wkh, wkl, wvh, wvl, bq, bk, bv, qp, kp, vp);

    norm_rope_kernel<<<dim3(S, 2), 256>>>(qp, kp, qh, ql, kh, kl, gq, gk, fc, fs);
    pool_mean<<<dim3(NB, 2), 256>>>(qp, kp, qwp, kwp);
    draft_scores<<<dim3(H, NB), 32>>>(qwp, kwp, bap);
    topk_thresh<<<H, 256>>>(bap, thp);
    build_lists<<<dim3(NB, H), 32>>>(bap, thp, lp, cp);
    order_pairs<<<1, H * NB>>>(cp, op);

    vt_split<<<dim3(S / 32, DIM / 32), 256>>>(vp, vth, vtl);

    attn_mma<<<H * NB, 256, ATT_SMEM>>>(qh, ql, kh, kl, vth, vtl, lp, cp, op, ah, al);

    // O projection
    gemm_mma<<<dim3(12, 24, 1), 256, GEMM_SMEM>>>(
        ah, al, woh, wol, woh, wol, woh, wol, bo, bo, bo, out, out, out);
}